// round 10
// baseline (speedup 1.0000x reference)
#include <cuda_runtime.h>
#include <cuda_bf16.h>
#include <cstdint>

#define EPSQ 1e-8f
static const int BATCH = 16;
static const int NI = 15488;

// ---------------- scratch ----------------
__device__ float g_c1f[(size_t)50176 * 256];
__device__ float g_c2f[(size_t)43264 * 256];
__device__ uint4 g_c1q[(size_t)50176 * 32];   // [pos][g(4)][A1 64B|A2 64B]
__device__ uint4 g_c2q[(size_t)43264 * 32];
__device__ uint4 g_w2q[(size_t)200 * 1024];   // [chunk*2+ntile][swz 128n x (W1 64|W2 64)]
__device__ uint4 g_wpq[(size_t)648 * 1024];
__device__ float g_part[(size_t)12 * 7744 * 256];
__device__ float g_p [(size_t)16 * 256 * 22 * 22];
__device__ float g_u [(size_t)16 * 15488 * 8];
__device__ __nv_bfloat16 g_uhatb[(size_t)16 * 15488 * 10 * 16];
__device__ float g_scales[4];   // 0=wmax2 1=wmaxp 2=amax_c1 3=amax_c2
__device__ float g_s[16 * 160];
__device__ float g_V[16 * 160];
__device__ float g_masked[16 * 160];
__device__ float g_d1[16 * 512];
__device__ float g_d2[16 * 1024];

// ---------------- helpers ----------------
__device__ __forceinline__ uint32_t smem_to_u32(const void* p) {
    uint32_t a;
    asm("{ .reg .u64 t; cvta.to.shared.u64 t, %1; cvt.u32.u64 %0, t; }" : "=r"(a) : "l"(p));
    return a;
}
__device__ __forceinline__ void ldsm_x4(uint32_t& r0, uint32_t& r1, uint32_t& r2, uint32_t& r3, uint32_t addr) {
    asm volatile("ldmatrix.sync.aligned.m8n8.x4.shared.b16 {%0,%1,%2,%3}, [%4];"
                 : "=r"(r0), "=r"(r1), "=r"(r2), "=r"(r3) : "r"(addr));
}
__device__ __forceinline__ void imma16832(int* c, const uint32_t* a, uint32_t b0, uint32_t b1) {
    asm volatile("mma.sync.aligned.m16n8k32.row.col.s32.s8.s8.s32 "
                 "{%0,%1,%2,%3}, {%4,%5,%6,%7}, {%8,%9}, {%0,%1,%2,%3};"
                 : "+r"(c[0]), "+r"(c[1]), "+r"(c[2]), "+r"(c[3])
                 : "r"(a[0]), "r"(a[1]), "r"(a[2]), "r"(a[3]), "r"(b0), "r"(b1));
}
#define CP_ASYNC16(dst, src, sz) \
    asm volatile("cp.async.cg.shared.global [%0], [%1], 16, %2;" :: "r"(dst), "l"(src), "r"(sz))
#define CP_COMMIT() asm volatile("cp.async.commit_group;" ::: "memory")
#define CP_WAIT(n)  asm volatile("cp.async.wait_group %0;" :: "n"(n) : "memory")

// ldmatrix x4 address: 16-row block at (base_r, base_c) in a [128 x 128B] swizzled image
__device__ __forceinline__ uint32_t lmaddr(uint32_t base, int lid, int base_r, int base_c) {
    int m = lid >> 3;
    int rr = base_r + ((m & 1) << 3) + (lid & 7);
    int cc = base_c + ((m >> 1) << 4);
    int off = rr * 128 + cc;
    return base + (off ^ ((rr & 7) << 4));
}

// ---------------- abs-max ----------------
__global__ void absmax_kernel(const float* __restrict__ x, int n, int sidx) {
    __shared__ int smax;
    if (threadIdx.x == 0) smax = 0;
    __syncthreads();
    float m = 0.f;
    for (int i = blockIdx.x * 256 + threadIdx.x; i < n; i += gridDim.x * 256)
        m = fmaxf(m, fabsf(x[i]));
    #pragma unroll
    for (int o = 16; o > 0; o >>= 1) m = fmaxf(m, __shfl_xor_sync(0xFFFFFFFF, m, o));
    if ((threadIdx.x & 31) == 0) atomicMax(&smax, __float_as_int(m));
    __syncthreads();
    if (threadIdx.x == 0) atomicMax((int*)&g_scales[sidx], smax);
}

// ---------------- weight quantize: fp32 -> swz [chunk][ntile][128n x (W1|W2)] ----------------
__global__ void transform_w_q(const float* __restrict__ w, uint4* __restrict__ wq,
                              int KH, int KW, int NCHUNK, int sidx) {
    int idx = blockIdx.x * 256 + threadIdx.x;
    int total = NCHUNK * 2 * 4096;
    if (idx >= total) return;
    int word = idx & 31;              // 32 u32 words per 128B row
    int n    = (idx >> 5) & 127;
    int img  = idx >> 12;             // chunk*2 + ntile
    int ntile = img & 1, chunk = img >> 1;
    int l = word >> 4;                // level
    int k4 = (word & 15) * 4;
    int kyx = chunk >> 2;
    int ky = kyx / KW, kx = kyx % KW;
    int oc = ntile * 128 + n;
    int icb = (chunk & 3) * 64 + k4;
    float inv = 16256.f / fmaxf(g_scales[sidx], 1e-30f);
    uint32_t out = 0;
    #pragma unroll
    for (int j = 0; j < 4; j++) {
        float q = w[(((size_t)oc * 256 + icb + j) * KH + ky) * KW + kx] * inv;
        float t1 = rintf(q * (1.f / 128.f));
        int v = (l == 0) ? (int)t1 : (int)rintf(q - 128.f * t1);
        out |= (uint32_t)(v & 0xff) << (8 * j);
    }
    int off = n * 128 + word * 4;
    int sw = off ^ ((n & 7) << 4);
    *(uint32_t*)((char*)(wq + (size_t)img * 1024) + sw) = out;
}

// ---------------- activation quantize: fp32 NHWC -> [pos][g][A1|A2] ----------------
__global__ void quantize_a(const float* __restrict__ in, uint4* __restrict__ outq,
                           int npos, int sidx) {
    int gid = blockIdx.x * 256 + threadIdx.x;
    if (gid >= npos * 64) return;
    int pos = gid >> 6, q = gid & 63;
    int g = q >> 4, c4 = (q & 15) * 4;
    float inv = 16256.f / fmaxf(g_scales[sidx], 1e-30f);
    float4 v = *(const float4*)(in + (size_t)pos * 256 + g * 64 + c4);
    float vv[4] = {v.x, v.y, v.z, v.w};
    uint32_t a1w = 0, a2w = 0;
    #pragma unroll
    for (int j = 0; j < 4; j++) {
        float qq = vv[j] * inv;
        float t1 = rintf(qq * (1.f / 128.f));
        a1w |= (uint32_t)((int)t1 & 0xff) << (8 * j);
        a2w |= (uint32_t)((int)rintf(qq - 128.f * t1) & 0xff) << (8 * j);
    }
    uint8_t* ob = (uint8_t*)outq + ((size_t)pos * 4 + g) * 128;
    *(uint32_t*)(ob + c4)      = a1w;
    *(uint32_t*)(ob + 64 + c4) = a2w;
}

// ---------------- conv1: fp32 NHWC out + amax ----------------
__global__ __launch_bounds__(196)
void conv1_kernel(const float* __restrict__ x, const float* __restrict__ w,
                  const float* __restrict__ bias, float* __restrict__ out) {
    __shared__ float s_in[36 * 36];
    __shared__ float s_w[4 * 81];
    __shared__ int smax;
    int tid = threadIdx.x;
    int tileY = blockIdx.x >> 1, tileX = blockIdx.x & 1;
    int b = blockIdx.z;
    int ocg = blockIdx.y;
    if (tid == 0) smax = 0;
    for (int idx = tid; idx < 1296; idx += 196) {
        int r = idx / 36, cc = idx % 36;
        s_in[idx] = x[((size_t)b * 64 + tileY * 28 + r) * 64 + tileX * 28 + cc];
    }
    int sy = tid / 14, sx = tid % 14;
    float tmax = 0.f;
    for (int oi = 0; oi < 32; oi += 4) {
        __syncthreads();
        for (int idx = tid; idx < 4 * 81; idx += 196) {
            int o = idx / 81, k = idx % 81;
            s_w[idx] = w[(size_t)(ocg * 32 + oi + o) * 81 + k];
        }
        __syncthreads();
        float acc[2][2][4];
        #pragma unroll
        for (int a = 0; a < 2; a++)
            #pragma unroll
            for (int q = 0; q < 2; q++)
                #pragma unroll
                for (int o = 0; o < 4; o++) acc[a][q][o] = 0.f;
        for (int ky = 0; ky < 9; ky++) {
            #pragma unroll
            for (int kx = 0; kx < 9; kx++) {
                int k = ky * 9 + kx;
                float w0 = s_w[k], w1 = s_w[81 + k], w2 = s_w[162 + k], w3 = s_w[243 + k];
                #pragma unroll
                for (int a = 0; a < 2; a++)
                    #pragma unroll
                    for (int q = 0; q < 2; q++) {
                        float v = s_in[(sy + 14 * a + ky) * 36 + sx + 14 * q + kx];
                        acc[a][q][0] += v * w0; acc[a][q][1] += v * w1;
                        acc[a][q][2] += v * w2; acc[a][q][3] += v * w3;
                    }
            }
        }
        int oc = ocg * 32 + oi;
        float b0 = bias[oc], b1 = bias[oc + 1], b2 = bias[oc + 2], b3 = bias[oc + 3];
        #pragma unroll
        for (int a = 0; a < 2; a++)
            #pragma unroll
            for (int q = 0; q < 2; q++) {
                int oy = tileY * 28 + a * 14 + sy;
                int ox = tileX * 28 + q * 14 + sx;
                size_t ob = ((size_t)(b * 56 + oy) * 56 + ox) * 256 + oc;
                float4 v4;
                v4.x = fmaxf(acc[a][q][0] + b0, 0.f);
                v4.y = fmaxf(acc[a][q][1] + b1, 0.f);
                v4.z = fmaxf(acc[a][q][2] + b2, 0.f);
                v4.w = fmaxf(acc[a][q][3] + b3, 0.f);
                tmax = fmaxf(tmax, fmaxf(fmaxf(v4.x, v4.y), fmaxf(v4.z, v4.w)));
                *(float4*)(out + ob) = v4;
            }
    }
    atomicMax(&smax, __float_as_int(tmax));
    __syncthreads();
    if (tid == 0) atomicMax((int*)&g_scales[2], smax);
}

// ---------------- IMMA implicit-GEMM conv ----------------
// 512 thr, 16 warps 4Mx4N; tile 128 pos x 128 oc (blockIdx.y = ntile); warp 32x32.
// Stage 32KB: A 16KB | B 16KB; 2 stages, single sync/chunk.
#define STG 32768
#define SMEM_CONV_TOTAL (2 * STG)

template<int IH, int IW, int OH, int OW, int KW, int STRIDE, int NCHUNK, int KSPLIT, int NPOS>
__global__ __launch_bounds__(512, 1)
void conv_imma_kernel(const uint4* __restrict__ inq4, const uint4* __restrict__ wq4,
                      float* __restrict__ part, int ia, int iw) {
    extern __shared__ char smem[];
    const uint32_t sb = smem_to_u32(smem);
    const char* inq = (const char*)inq4;
    const char* wq  = (const char*)wq4;
    const int tid = threadIdx.x;
    const int wid = tid >> 5, lid = tid & 31;
    const int tile = blockIdx.x, ntile = blockIdx.y;

    const int r = tid >> 2, sp = tid & 3;    // A fill: 4 thr/row, 2x16B each
    const int p_mine = tile * 128 + r;
    const bool pvalid = p_mine < NPOS;
    int pb = 0, pr = 0, pcx = 0;
    if (pvalid) {
        pb = p_mine / (OH * OW);
        int rem = p_mine - pb * (OH * OW);
        pr = rem / OW;
        pcx = rem - pr * OW;
    }
    const int asz = pvalid ? 16 : 0;

    const int wm = wid >> 2, wn = wid & 3;
    const int gid = lid >> 2, tig = lid & 3;

    int S11[2][4][4], S12[2][4][4];
    #pragma unroll
    for (int ma = 0; ma < 2; ma++)
        #pragma unroll
        for (int nt = 0; nt < 4; nt++)
            #pragma unroll
            for (int q = 0; q < 4; q++) { S11[ma][nt][q] = 0; S12[ma][nt][q] = 0; }

    const int NC = NCHUNK / KSPLIT;
    const int coff = blockIdx.z * NC;

    auto fill = [&](int stage, int chunk) {
        uint32_t s0 = sb + stage * STG;
        const char* bsrc = wq + (size_t)(chunk * 2 + ntile) * 16384;
        CP_ASYNC16(s0 + 16384 + tid * 16, bsrc + tid * 16, 16);
        CP_ASYNC16(s0 + 24576 + tid * 16, bsrc + 8192 + tid * 16, 16);
        const int kyx = chunk >> 2;
        const int g = chunk & 3;
        const int ky = kyx / KW, kx = kyx % KW;
        const char* src = inq;
        if (pvalid) {
            int iy = pr * STRIDE + ky, ix = pcx * STRIDE + kx;
            src = inq + ((size_t)((pb * IH + iy) * IW + ix) * 4 + g) * 128;
        }
        #pragma unroll
        for (int q = 0; q < 2; q++) {
            int seg = sp * 2 + q;
            uint32_t off = r * 128 + seg * 16;
            uint32_t sw = off ^ ((r & 7) << 4);
            CP_ASYNC16(s0 + sw, src + seg * 16, asz);
        }
    };

    fill(0, coff);
    CP_COMMIT();

    for (int i = 0; i < NC; ++i) {
        CP_WAIT(0);
        __syncthreads();
        if (i + 1 < NC) { fill((i + 1) & 1, coff + i + 1); CP_COMMIT(); }

        const uint32_t sA = sb + (i & 1) * STG;
        const uint32_t sB = sA + 16384;
        #pragma unroll
        for (int ks = 0; ks < 2; ks++) {
            uint32_t B1[4][2], B2[4][2];
            #pragma unroll
            for (int ng = 0; ng < 2; ng++) {
                ldsm_x4(B1[ng*2][0], B1[ng*2+1][0], B1[ng*2][1], B1[ng*2+1][1],
                        lmaddr(sB, lid, wn * 32 + ng * 16, ks * 32));
                ldsm_x4(B2[ng*2][0], B2[ng*2+1][0], B2[ng*2][1], B2[ng*2+1][1],
                        lmaddr(sB, lid, wn * 32 + ng * 16, 64 + ks * 32));
            }
            #pragma unroll
            for (int ma = 0; ma < 2; ma++) {
                uint32_t a1[4], a2[4];
                ldsm_x4(a1[0], a1[1], a1[2], a1[3], lmaddr(sA, lid, wm * 32 + ma * 16, ks * 32));
                ldsm_x4(a2[0], a2[1], a2[2], a2[3], lmaddr(sA, lid, wm * 32 + ma * 16, 64 + ks * 32));
                #pragma unroll
                for (int nt = 0; nt < 4; nt++) {
                    imma16832(S11[ma][nt], a1, B1[nt][0], B1[nt][1]);
                    imma16832(S12[ma][nt], a1, B2[nt][0], B2[nt][1]);
                    imma16832(S12[ma][nt], a2, B1[nt][0], B1[nt][1]);
                }
            }
        }
    }

    // epilogue: y = sc*(16384*S11 + 128*S12), fp32 partials
    float sc = g_scales[ia] * g_scales[iw] * (1.f / (16256.f * 16256.f));
    float* op0 = part + (size_t)blockIdx.z * NPOS * 256;
    #pragma unroll
    for (int ma = 0; ma < 2; ma++)
        #pragma unroll
        for (int h = 0; h < 2; h++) {
            int p = tile * 128 + wm * 32 + ma * 16 + h * 8 + gid;
            if (p >= NPOS) continue;
            float* op = op0 + (size_t)p * 256 + ntile * 128 + wn * 32 + tig * 2;
            #pragma unroll
            for (int nt = 0; nt < 4; nt++) {
                float v0 = sc * (16384.f * (float)S11[ma][nt][h*2]   + 128.f * (float)S12[ma][nt][h*2]);
                float v1 = sc * (16384.f * (float)S11[ma][nt][h*2+1] + 128.f * (float)S12[ma][nt][h*2+1]);
                *(float2*)(op + nt * 8) = make_float2(v0, v1);
            }
        }
}

// ---------------- reduce conv2 (2-way) -> bias+relu -> fp32 NHWC + amax ----------------
__global__ void reduce2_kernel(const float* __restrict__ part, const float* __restrict__ bias,
                               float* __restrict__ out) {
    __shared__ int smax;
    if (threadIdx.x == 0) smax = 0;
    __syncthreads();
    size_t gid = (size_t)blockIdx.x * 256 + threadIdx.x;
    float m = 0.f;
    if (gid < (size_t)43264 * 128) {
        int p = (int)(gid >> 7);
        int oc = ((int)gid & 127) * 2;
        const float* p0 = part + (size_t)p * 256 + oc;
        const size_t half = (size_t)43264 * 256;
        float v0 = fmaxf(p0[0] + p0[half]     + bias[oc],     0.f);
        float v1 = fmaxf(p0[1] + p0[half + 1] + bias[oc + 1], 0.f);
        *(float2*)(out + (size_t)p * 256 + oc) = make_float2(v0, v1);
        m = fmaxf(v0, v1);
    }
    #pragma unroll
    for (int o = 16; o > 0; o >>= 1) m = fmaxf(m, __shfl_xor_sync(0xFFFFFFFF, m, o));
    if ((threadIdx.x & 31) == 0) atomicMax(&smax, __float_as_int(m));
    __syncthreads();
    if (threadIdx.x == 0) atomicMax((int*)&g_scales[3], smax);
}

// ---------------- reduce pc partials (12-way) -> bias -> fp32 NCHW ----------------
__global__ void reducep_kernel(const float* __restrict__ part, const float* __restrict__ bias,
                               float* __restrict__ out) {
    int gid = blockIdx.x * 256 + threadIdx.x;
    if (gid >= 7744 * 64) return;
    int p = gid >> 6, oc = (gid & 63) * 4;
    const size_t seg = (size_t)7744 * 256;
    const float* p0 = part + (size_t)p * 256 + oc;
    float4 v = *(const float4*)p0;
    #pragma unroll
    for (int k = 1; k < 12; k++) {
        float4 t = *(const float4*)(p0 + k * seg);
        v.x += t.x; v.y += t.y; v.z += t.z; v.w += t.w;
    }
    const float4 bv = *(const float4*)(bias + oc);
    v.x += bv.x; v.y += bv.y; v.z += bv.z; v.w += bv.w;
    int b = p / 484;
    int rem = p - b * 484;
    int rr = rem / 22, cx = rem - rr * 22;
    size_t base = (((size_t)b * 256 + oc) * 22 + rr) * 22 + cx;
    out[base] = v.x; out[base + 484] = v.y;
    out[base + 2 * 484] = v.z; out[base + 3 * 484] = v.w;
}

// ---------------- squash / u_hat / routing / v_update / fc (unchanged) ----------------
__global__ void squash_u_kernel() {
    int cap = blockIdx.x * 256 + threadIdx.x;
    if (cap >= BATCH * NI) return;
    const float4* pp = (const float4*)(g_p + (size_t)cap * 8);
    float4 a = pp[0], c = pp[1];
    float s2 = a.x*a.x + a.y*a.y + a.z*a.z + a.w*a.w + c.x*c.x + c.y*c.y + c.z*c.z + c.w*c.w;
    float f = s2 / (1.f + s2) * rsqrtf(s2 + EPSQ);
    a.x *= f; a.y *= f; a.z *= f; a.w *= f;
    c.x *= f; c.y *= f; c.z *= f; c.w *= f;
    float4* uo = (float4*)(g_u + (size_t)cap * 8);
    uo[0] = a; uo[1] = c;
}

__global__ __launch_bounds__(256)
void uhat_kernel(const float* __restrict__ W) {
    int gid = blockIdx.x * 256 + threadIdx.x;
    int d = gid & 15;
    int j = (gid >> 4) % 10;
    int i = gid / 160;
    if (i >= NI) return;
    const float4* Wp = (const float4*)(W + (((size_t)j * NI + i) * 16 + d) * 8);
    float4 w0 = Wp[0], w1 = Wp[1];
    for (int b = 0; b < BATCH; b++) {
        const float4* up = (const float4*)(g_u + ((size_t)b * NI + i) * 8);
        float4 u0 = up[0], u1 = up[1];
        float acc = w0.x*u0.x + w0.y*u0.y + w0.z*u0.z + w0.w*u0.w
                  + w1.x*u1.x + w1.y*u1.y + w1.z*u1.z + w1.w*u1.w;
        g_uhatb[(((size_t)b * NI + i) * 10 + j) * 16 + d] = __float2bfloat16(acc);
    }
}

__global__ __launch_bounds__(256)
void routing_s_kernel() {
    __shared__ float Vsh[160];
    __shared__ float ssh[160];
    int tid = threadIdx.x;
    int b = blockIdx.y;
    if (tid < 160) { Vsh[tid] = g_V[b * 160 + tid]; ssh[tid] = 0.f; }
    __syncthreads();
    int d = tid & 15, il = tid >> 4;
    float accj[10];
    #pragma unroll
    for (int j = 0; j < 10; j++) accj[j] = 0.f;
    const int per = NI / 32;
    int i0 = blockIdx.x * per;
    for (int i = i0 + il; i < i0 + per; i += 16) {
        const __nv_bfloat16* uh = g_uhatb + (((size_t)b * NI + i) * 10) * 16 + d;
        float uv[10], e[10];
        float m = -1e30f;
        #pragma unroll
        for (int j = 0; j < 10; j++) {
            uv[j] = __bfloat162float(uh[j * 16]);
            float l = uv[j] * Vsh[j * 16 + d];
            e[j] = l;
            m = fmaxf(m, l);
        }
        float se = 0.f;
        #pragma unroll
        for (int j = 0; j < 10; j++) { e[j] = __expf(e[j] - m); se += e[j]; }
        float inv = 1.f / se;
        #pragma unroll
        for (int j = 0; j < 10; j++) accj[j] += e[j] * inv * uv[j];
    }
    #pragma unroll
    for (int j = 0; j < 10; j++) atomicAdd(&ssh[j * 16 + d], accj[j]);
    __syncthreads();
    if (tid < 160) atomicAdd(&g_s[b * 160 + tid], ssh[tid]);
}

__global__ void v_update_kernel(int last, float* __restrict__ dout) {
    __shared__ float s2sh[10];
    __shared__ float nrm[10];
    __shared__ int amax;
    int b = blockIdx.x, tid = threadIdx.x;
    int j = tid >> 4, d = tid & 15;
    if (tid < 10) s2sh[tid] = 0.f;
    __syncthreads();
    float sv = g_s[b * 160 + tid];
    atomicAdd(&s2sh[j], sv * sv);
    __syncthreads();
    float s2 = s2sh[j];
    float v = s2 / (1.f + s2) * sv * rsqrtf(s2 + EPSQ);
    if (!last) {
        g_V[b * 160 + tid] += v;
    } else {
        if (d == 0) nrm[j] = s2 / (1.f + s2) * sqrtf(s2) * rsqrtf(s2 + EPSQ);
        __syncthreads();
        if (tid == 0) {
            int bm = 0; float mx = nrm[0];
            for (int jj = 1; jj < 10; jj++)
                if (nrm[jj] > mx) { mx = nrm[jj]; bm = jj; }
            amax = bm;
        }
        if (d == 0) dout[b * 10 + j] = nrm[j];
        __syncthreads();
        g_masked[b * 160 + tid] = (j == amax) ? v : 0.f;
    }
}

__global__ void fc_kernel(const float* __restrict__ in, const float* __restrict__ W,
                          const float* __restrict__ bias, float* __restrict__ out,
                          int IN, int OUT, int act) {
    int gid = blockIdx.x * blockDim.x + threadIdx.x;
    if (gid >= BATCH * OUT) return;
    int o = gid % OUT, b = gid / OUT;
    const float* ip = in + (size_t)b * IN;
    float acc = bias[o];
    for (int k = 0; k < IN; k++) acc += ip[k] * W[(size_t)k * OUT + o];
    if (act == 1) acc = fmaxf(acc, 0.f);
    else          acc = 1.f / (1.f + __expf(-acc));
    out[gid] = acc;
}

// ---------------- launch ----------------
extern "C" void kernel_launch(void* const* d_in, const int* in_sizes, int n_in,
                              void* d_out, int out_size) {
    const float* x   = (const float*)d_in[0];
    const float* c1w = (const float*)d_in[1];
    const float* c1b = (const float*)d_in[2];
    const float* c2w = (const float*)d_in[3];
    const float* c2b = (const float*)d_in[4];
    const float* pcw = (const float*)d_in[5];
    const float* pcb = (const float*)d_in[6];
    const float* Wc  = (const float*)d_in[7];
    const float* w1  = (const float*)d_in[8];
    const float* b1  = (const float*)d_in[9];
    const float* w2  = (const float*)d_in[10];
    const float* b2  = (const float*)d_in[11];
    const float* w3  = (const float*)d_in[12];
    const float* b3  = (const float*)d_in[13];
    float* dout = (float*)d_out;

    float *p_c1f, *p_c2f, *p_part, *p_p, *p_s, *p_V, *p_masked, *p_d1, *p_d2, *p_scales;
    uint4 *p_c1q, *p_c2q, *p_w2q, *p_wpq;
    cudaGetSymbolAddress((void**)&p_c1f, g_c1f);
    cudaGetSymbolAddress((void**)&p_c2f, g_c2f);
    cudaGetSymbolAddress((void**)&p_c1q, g_c1q);
    cudaGetSymbolAddress((void**)&p_c2q, g_c2q);
    cudaGetSymbolAddress((void**)&p_w2q, g_w2q);
    cudaGetSymbolAddress((void**)&p_wpq, g_wpq);
    cudaGetSymbolAddress((void**)&p_part, g_part);
    cudaGetSymbolAddress((void**)&p_p,  g_p);
    cudaGetSymbolAddress((void**)&p_s,  g_s);
    cudaGetSymbolAddress((void**)&p_V,  g_V);
    cudaGetSymbolAddress((void**)&p_masked, g_masked);
    cudaGetSymbolAddress((void**)&p_d1, g_d1);
    cudaGetSymbolAddress((void**)&p_d2, g_d2);
    cudaGetSymbolAddress((void**)&p_scales, g_scales);

    auto conv2 = conv_imma_kernel<56, 56, 52, 52, 5, 1, 100, 2, 43264>;
    auto convp = conv_imma_kernel<52, 52, 22, 22, 9, 2, 324, 12, 7744>;
    cudaFuncSetAttribute(conv2, cudaFuncAttributeMaxDynamicSharedMemorySize, SMEM_CONV_TOTAL);
    cudaFuncSetAttribute(convp, cudaFuncAttributeMaxDynamicSharedMemorySize, SMEM_CONV_TOTAL);

    cudaMemsetAsync(p_scales, 0, 4 * sizeof(float));
    absmax_kernel<<<256, 256>>>(c2w, 256 * 256 * 25, 0);
    absmax_kernel<<<256, 256>>>(pcw, 256 * 256 * 81, 1);
    transform_w_q<<<(100 * 8192 + 255) / 256, 256>>>(c2w, p_w2q, 5, 5, 100, 0);
    transform_w_q<<<(324 * 8192 + 255) / 256, 256>>>(pcw, p_wpq, 9, 9, 324, 1);

    conv1_kernel<<<dim3(4, 8, 16), 196>>>(x, c1w, c1b, p_c1f);
    quantize_a<<<(50176 * 64 + 255) / 256, 256>>>(p_c1f, p_c1q, 50176, 2);

    conv2<<<dim3(338, 2, 2), 512, SMEM_CONV_TOTAL>>>(p_c1q, p_w2q, p_part, 2, 0);
    reduce2_kernel<<<(int)(((size_t)43264 * 128 + 255) / 256), 256>>>(p_part, c2b, p_c2f);
    quantize_a<<<(43264 * 64 + 255) / 256, 256>>>(p_c2f, p_c2q, 43264, 3);

    convp<<<dim3(61, 2, 12), 512, SMEM_CONV_TOTAL>>>(p_c2q, p_wpq, p_part, 3, 1);
    reducep_kernel<<<(7744 * 64 + 255) / 256, 256>>>(p_part, pcb, p_p);

    squash_u_kernel<<<(BATCH * NI + 255) / 256, 256>>>();
    uhat_kernel<<<((size_t)NI * 160 + 255) / 256, 256>>>(Wc);

    cudaMemsetAsync(p_V, 0, BATCH * 160 * sizeof(float));
    for (int r = 0; r < 3; r++) {
        cudaMemsetAsync(p_s, 0, BATCH * 160 * sizeof(float));
        routing_s_kernel<<<dim3(32, 16), 256>>>();
        v_update_kernel<<<16, 160>>>(r == 2 ? 1 : 0, dout);
    }

    fc_kernel<<<(BATCH * 512 + 255) / 256, 256>>>(p_masked, w1, b1, p_d1, 160, 512, 1);
    fc_kernel<<<(BATCH * 1024 + 255) / 256, 256>>>(p_d1, w2, b2, p_d2, 512, 1024, 1);
    fc_kernel<<<(BATCH * 4096 + 255) / 256, 256>>>(p_d2, w3, b3, dout + 160, 1024, 4096, 2);
}

// round 11
// speedup vs baseline: 3.2217x; 3.2217x over previous
#include <cuda_runtime.h>
#include <cuda_bf16.h>
#include <cstdint>

#define EPSQ 1e-8f
static const int BATCH = 16;
static const int NI = 15488;

// ---------------- scratch ----------------
__device__ __nv_bfloat16 g_c1b[(size_t)50176 * 256];   // conv1 out, bf16 NHWC
__device__ __nv_bfloat16 g_c2b[(size_t)43264 * 256];
__device__ float g_part[(size_t)12 * 7744 * 256];      // split-K partials (conv2 uses 2*43264*256 = 88MB)
__device__ float g_p [(size_t)16 * 256 * 22 * 22];
__device__ float g_u [(size_t)16 * 15488 * 8];
__device__ __nv_bfloat16 g_uhatb[(size_t)16 * 15488 * 10 * 16];
__device__ __nv_bfloat16 g_w2h[(size_t)100 * 16384];   // [chunk][64k x 256n swizzled]
__device__ __nv_bfloat16 g_w2l[(size_t)100 * 16384];
__device__ __nv_bfloat16 g_wph[(size_t)324 * 16384];
__device__ __nv_bfloat16 g_wpl[(size_t)324 * 16384];
__device__ float g_s[16 * 160];
__device__ float g_V[16 * 160];
__device__ float g_masked[16 * 160];
__device__ float g_d1[16 * 512];
__device__ float g_d2[16 * 1024];

// ---------------- helpers ----------------
__device__ __forceinline__ uint32_t smem_to_u32(const void* p) {
    uint32_t a;
    asm("{ .reg .u64 t; cvta.to.shared.u64 t, %1; cvt.u32.u64 %0, t; }" : "=r"(a) : "l"(p));
    return a;
}
__device__ __forceinline__ void ldsm_x4(uint32_t& r0, uint32_t& r1, uint32_t& r2, uint32_t& r3, uint32_t addr) {
    asm volatile("ldmatrix.sync.aligned.m8n8.x4.shared.b16 {%0,%1,%2,%3}, [%4];"
                 : "=r"(r0), "=r"(r1), "=r"(r2), "=r"(r3) : "r"(addr));
}
__device__ __forceinline__ void ldsm_x4_t(uint32_t& r0, uint32_t& r1, uint32_t& r2, uint32_t& r3, uint32_t addr) {
    asm volatile("ldmatrix.sync.aligned.m8n8.x4.trans.shared.b16 {%0,%1,%2,%3}, [%4];"
                 : "=r"(r0), "=r"(r1), "=r"(r2), "=r"(r3) : "r"(addr));
}
__device__ __forceinline__ void mma16816(float* c, const uint32_t* a, const uint32_t* b) {
    asm volatile("mma.sync.aligned.m16n8k16.row.col.f32.bf16.bf16.f32 "
                 "{%0,%1,%2,%3}, {%4,%5,%6,%7}, {%8,%9}, {%0,%1,%2,%3};"
                 : "+f"(c[0]), "+f"(c[1]), "+f"(c[2]), "+f"(c[3])
                 : "r"(a[0]), "r"(a[1]), "r"(a[2]), "r"(a[3]), "r"(b[0]), "r"(b[1]));
}
#define CP_ASYNC16(dst, src, sz) \
    asm volatile("cp.async.cg.shared.global [%0], [%1], 16, %2;" :: "r"(dst), "l"(src), "r"(sz))
#define CP_COMMIT() asm volatile("cp.async.commit_group;" ::: "memory")
#define CP_WAIT(n)  asm volatile("cp.async.wait_group %0;" :: "n"(n) : "memory")

// ---------------- weight split+swizzle: [chunk][64k x 256n bf16, 512B rows, XOR (k&7)<<4] ----------------
__global__ void transform_wsplit_kernel(const float* __restrict__ w,
                                        __nv_bfloat16* __restrict__ wh,
                                        __nv_bfloat16* __restrict__ wl,
                                        int KH, int KW, int NCHUNK) {
    int idx = blockIdx.x * 256 + threadIdx.x;
    int total = NCHUNK * 64 * 128;
    if (idx >= total) return;
    int np = idx & 127;
    int k  = (idx >> 7) & 63;
    int chunk = idx >> 13;
    int kyx = chunk >> 2;
    int ic = (chunk & 3) * 64 + k;
    int ky = kyx / KW, kx = kyx % KW;
    int oc = np * 2;
    size_t KHW = (size_t)KH * KW;
    size_t wi = (((size_t)oc * 256 + ic) * KH + ky) * KW + kx;
    float f0 = w[wi];
    float f1 = w[wi + 256 * KHW];
    __nv_bfloat16 h0 = __float2bfloat16(f0);
    __nv_bfloat16 h1 = __float2bfloat16(f1);
    __nv_bfloat16 l0 = __float2bfloat16(f0 - __bfloat162float(h0));
    __nv_bfloat16 l1 = __float2bfloat16(f1 - __bfloat162float(h1));
    uint32_t hp = ((uint32_t)__bfloat16_as_ushort(h1) << 16) | __bfloat16_as_ushort(h0);
    uint32_t lp = ((uint32_t)__bfloat16_as_ushort(l1) << 16) | __bfloat16_as_ushort(l0);
    int off = k * 512 + np * 4;
    int sw = off ^ ((k & 7) << 4);
    size_t tb = (size_t)chunk * 32768;
    *(uint32_t*)((char*)wh + tb + sw) = hp;
    *(uint32_t*)((char*)wl + tb + sw) = lp;
}

// ---------------- conv1: 1->256, 9x9, s1, NHWC bf16 out ----------------
__global__ __launch_bounds__(196)
void conv1_kernel(const float* __restrict__ x, const float* __restrict__ w,
                  const float* __restrict__ bias, __nv_bfloat16* __restrict__ ob16) {
    __shared__ float s_in[36 * 36];
    __shared__ float s_w[4 * 81];
    int tid = threadIdx.x;
    int tileY = blockIdx.x >> 1, tileX = blockIdx.x & 1;
    int b = blockIdx.z;
    int ocg = blockIdx.y;
    for (int idx = tid; idx < 1296; idx += 196) {
        int r = idx / 36, cc = idx % 36;
        s_in[idx] = x[((size_t)b * 64 + tileY * 28 + r) * 64 + tileX * 28 + cc];
    }
    int sy = tid / 14, sx = tid % 14;
    for (int oi = 0; oi < 32; oi += 4) {
        __syncthreads();
        for (int idx = tid; idx < 4 * 81; idx += 196) {
            int o = idx / 81, k = idx % 81;
            s_w[idx] = w[(size_t)(ocg * 32 + oi + o) * 81 + k];
        }
        __syncthreads();
        float acc[2][2][4];
        #pragma unroll
        for (int a = 0; a < 2; a++)
            #pragma unroll
            for (int q = 0; q < 2; q++)
                #pragma unroll
                for (int o = 0; o < 4; o++) acc[a][q][o] = 0.f;
        for (int ky = 0; ky < 9; ky++) {
            #pragma unroll
            for (int kx = 0; kx < 9; kx++) {
                int k = ky * 9 + kx;
                float w0 = s_w[k], w1 = s_w[81 + k], w2 = s_w[162 + k], w3 = s_w[243 + k];
                #pragma unroll
                for (int a = 0; a < 2; a++)
                    #pragma unroll
                    for (int q = 0; q < 2; q++) {
                        float v = s_in[(sy + 14 * a + ky) * 36 + sx + 14 * q + kx];
                        acc[a][q][0] += v * w0; acc[a][q][1] += v * w1;
                        acc[a][q][2] += v * w2; acc[a][q][3] += v * w3;
                    }
            }
        }
        int oc = ocg * 32 + oi;
        float b0 = bias[oc], b1 = bias[oc + 1], b2 = bias[oc + 2], b3 = bias[oc + 3];
        #pragma unroll
        for (int a = 0; a < 2; a++)
            #pragma unroll
            for (int q = 0; q < 2; q++) {
                int oy = tileY * 28 + a * 14 + sy;
                int ox = tileX * 28 + q * 14 + sx;
                size_t ob = ((size_t)(b * 56 + oy) * 56 + ox) * 256 + oc;
                ushort h0 = __bfloat16_as_ushort(__float2bfloat16(fmaxf(acc[a][q][0] + b0, 0.f)));
                ushort h1 = __bfloat16_as_ushort(__float2bfloat16(fmaxf(acc[a][q][1] + b1, 0.f)));
                ushort h2 = __bfloat16_as_ushort(__float2bfloat16(fmaxf(acc[a][q][2] + b2, 0.f)));
                ushort h3 = __bfloat16_as_ushort(__float2bfloat16(fmaxf(acc[a][q][3] + b3, 0.f)));
                *(uint2*)(ob16 + ob) = make_uint2(((uint32_t)h1 << 16) | h0,
                                                  ((uint32_t)h3 << 16) | h2);
            }
    }
}

// ---------------- HMMA implicit-GEMM conv, 2-term (a*Wh + a*Wl), 2-stage, one sync/chunk ----------------
// Block 512 thr (16 warps 4Mx4N); tile M=128 pos x N=256 oc; warp 32x64.
// Stage 80KB: A 16K | Bh 32K | Bl 32K.
#define STG_STRIDE 81920
#define SMEM_CONV_TOTAL (2 * STG_STRIDE)

template<int IH, int IW, int OH, int OW, int KW, int STRIDE, int NCHUNK, int KSPLIT, int NPOS>
__global__ __launch_bounds__(512, 1)
void conv_mma_kernel(const __nv_bfloat16* __restrict__ inb,
                     const __nv_bfloat16* __restrict__ wh,
                     const __nv_bfloat16* __restrict__ wl,
                     float* __restrict__ part) {
    extern __shared__ char smem[];
    const uint32_t sb = smem_to_u32(smem);
    const int tid = threadIdx.x;
    const int wid = tid >> 5, lid = tid & 31;
    const int tile = blockIdx.x;

    const int r = tid >> 2, sp = tid & 3;    // A fill: 4 thr/row, 2x16B each
    const int p_mine = tile * 128 + r;
    const bool pvalid = p_mine < NPOS;
    int pb = 0, pr = 0, pcx = 0;
    if (pvalid) {
        pb = p_mine / (OH * OW);
        int rem = p_mine - pb * (OH * OW);
        pr = rem / OW;
        pcx = rem - pr * OW;
    }
    const int asz = pvalid ? 16 : 0;

    const int wm = wid >> 2, wn = wid & 3;
    const int lane15 = lid & 15, lane16 = lid >> 4;
    const int gid = lid >> 2, tig = lid & 3;

    float acc[2][8][4];
    #pragma unroll
    for (int ma = 0; ma < 2; ma++)
        #pragma unroll
        for (int na = 0; na < 8; na++)
            #pragma unroll
            for (int q = 0; q < 4; q++) acc[ma][na][q] = 0.f;

    const int NC = NCHUNK / KSPLIT;
    const int coff = blockIdx.y * NC;

    auto fill = [&](int stage, int chunk) {
        uint32_t s0 = sb + stage * STG_STRIDE;
        const char* bh = (const char*)(wh + (size_t)chunk * 16384);
        const char* bl = (const char*)(wl + (size_t)chunk * 16384);
        #pragma unroll
        for (int i = 0; i < 4; i++) {
            uint32_t u = (tid + i * 512) * 16;
            CP_ASYNC16(s0 + 16384 + u, bh + u, 16);
            CP_ASYNC16(s0 + 49152 + u, bl + u, 16);
        }
        const int kyx = chunk >> 2;
        const int ic0 = (chunk & 3) * 64;
        const int ky = kyx / KW, kx = kyx % KW;
        size_t srcbase = 0;
        if (pvalid) {
            int iy = pr * STRIDE + ky, ix = pcx * STRIDE + kx;
            srcbase = (((size_t)pb * IH + iy) * IW + ix) * 256 + ic0;
        }
        #pragma unroll
        for (int q = 0; q < 2; q++) {
            int seg = sp * 2 + q;
            uint32_t off = r * 128 + seg * 16;
            uint32_t sw = off ^ ((r & 7) << 4);
            CP_ASYNC16(s0 + sw, (const char*)(inb + srcbase + seg * 8), asz);
        }
    };

    fill(0, coff);
    CP_COMMIT();

    for (int i = 0; i < NC; ++i) {
        CP_WAIT(0);
        __syncthreads();
        if (i + 1 < NC) { fill((i + 1) & 1, coff + i + 1); CP_COMMIT(); }

        const uint32_t s0 = sb + (i & 1) * STG_STRIDE;
        #pragma unroll
        for (int ks = 0; ks < 4; ks++) {
            uint32_t Bh[8][2], Bl[8][2];
            const int brow = ks * 16 + lane15;
            #pragma unroll
            for (int q = 0; q < 4; q++) {
                uint32_t off = brow * 512 + wn * 128 + q * 32 + lane16 * 16;
                uint32_t sw = off ^ ((brow & 7) << 4);
                ldsm_x4_t(Bh[2*q][0], Bh[2*q][1], Bh[2*q+1][0], Bh[2*q+1][1], s0 + 16384 + sw);
                ldsm_x4_t(Bl[2*q][0], Bl[2*q][1], Bl[2*q+1][0], Bl[2*q+1][1], s0 + 49152 + sw);
            }
            #pragma unroll
            for (int ma = 0; ma < 2; ma++) {
                const int arow = wm * 32 + ma * 16 + lane15;
                uint32_t offA = arow * 128 + ks * 32 + lane16 * 16;
                uint32_t swA = offA ^ ((arow & 7) << 4);
                uint32_t a[4];
                ldsm_x4(a[0], a[1], a[2], a[3], s0 + swA);
                #pragma unroll
                for (int na = 0; na < 8; na++) mma16816(acc[ma][na], a, Bh[na]);
                #pragma unroll
                for (int na = 0; na < 8; na++) mma16816(acc[ma][na], a, Bl[na]);
            }
        }
    }

    float* op0 = part + (size_t)blockIdx.y * NPOS * 256;
    #pragma unroll
    for (int ma = 0; ma < 2; ma++)
        #pragma unroll
        for (int h = 0; h < 2; h++) {
            int p = tile * 128 + wm * 32 + ma * 16 + h * 8 + gid;
            if (p >= NPOS) continue;
            float* op = op0 + (size_t)p * 256 + wn * 64 + tig * 2;
            #pragma unroll
            for (int na = 0; na < 8; na++)
                *(float2*)(op + na * 8) = make_float2(acc[ma][na][h * 2], acc[ma][na][h * 2 + 1]);
        }
}

// ---------------- reduce conv2 (2-way) -> bias+relu -> bf16 NHWC ----------------
__global__ void reduce2_kernel(const float* __restrict__ part, const float* __restrict__ bias,
                               __nv_bfloat16* __restrict__ ob16) {
    size_t gid = (size_t)blockIdx.x * 256 + threadIdx.x;
    if (gid >= (size_t)43264 * 128) return;
    int p = (int)(gid >> 7);
    int oc = ((int)gid & 127) * 2;
    const float* p0 = part + (size_t)p * 256 + oc;
    const size_t half = (size_t)43264 * 256;
    float v0 = fmaxf(p0[0] + p0[half]     + bias[oc],     0.f);
    float v1 = fmaxf(p0[1] + p0[half + 1] + bias[oc + 1], 0.f);
    uint32_t w = ((uint32_t)__bfloat16_as_ushort(__float2bfloat16(v1)) << 16)
               | __bfloat16_as_ushort(__float2bfloat16(v0));
    *(uint32_t*)(ob16 + (size_t)p * 256 + oc) = w;
}

// ---------------- reduce pc partials (12-way) -> bias -> fp32 NCHW ----------------
__global__ void reducep_kernel(const float* __restrict__ part, const float* __restrict__ bias,
                               float* __restrict__ out) {
    int gid = blockIdx.x * 256 + threadIdx.x;
    if (gid >= 7744 * 64) return;
    int p = gid >> 6, oc = (gid & 63) * 4;
    const size_t seg = (size_t)7744 * 256;
    const float* p0 = part + (size_t)p * 256 + oc;
    float4 v = *(const float4*)p0;
    #pragma unroll
    for (int k = 1; k < 12; k++) {
        float4 t = *(const float4*)(p0 + k * seg);
        v.x += t.x; v.y += t.y; v.z += t.z; v.w += t.w;
    }
    const float4 bv = *(const float4*)(bias + oc);
    v.x += bv.x; v.y += bv.y; v.z += bv.z; v.w += bv.w;
    int b = p / 484;
    int rem = p - b * 484;
    int rr = rem / 22, cx = rem - rr * 22;
    size_t base = (((size_t)b * 256 + oc) * 22 + rr) * 22 + cx;
    out[base] = v.x; out[base + 484] = v.y;
    out[base + 2 * 484] = v.z; out[base + 3 * 484] = v.w;
}

// ---------------- squash / u_hat / routing / v_update / fc ----------------
__global__ void squash_u_kernel() {
    int cap = blockIdx.x * 256 + threadIdx.x;
    if (cap >= BATCH * NI) return;
    const float4* pp = (const float4*)(g_p + (size_t)cap * 8);
    float4 a = pp[0], c = pp[1];
    float s2 = a.x*a.x + a.y*a.y + a.z*a.z + a.w*a.w + c.x*c.x + c.y*c.y + c.z*c.z + c.w*c.w;
    float f = s2 / (1.f + s2) * rsqrtf(s2 + EPSQ);
    a.x *= f; a.y *= f; a.z *= f; a.w *= f;
    c.x *= f; c.y *= f; c.z *= f; c.w *= f;
    float4* uo = (float4*)(g_u + (size_t)cap * 8);
    uo[0] = a; uo[1] = c;
}

__global__ __launch_bounds__(256)
void uhat_kernel(const float* __restrict__ W) {
    int gid = blockIdx.x * 256 + threadIdx.x;
    int d = gid & 15;
    int j = (gid >> 4) % 10;
    int i = gid / 160;
    if (i >= NI) return;
    const float4* Wp = (const float4*)(W + (((size_t)j * NI + i) * 16 + d) * 8);
    float4 w0 = Wp[0], w1 = Wp[1];
    for (int b = 0; b < BATCH; b++) {
        const float4* up = (const float4*)(g_u + ((size_t)b * NI + i) * 8);
        float4 u0 = up[0], u1 = up[1];
        float acc = w0.x*u0.x + w0.y*u0.y + w0.z*u0.z + w0.w*u0.w
                  + w1.x*u1.x + w1.y*u1.y + w1.z*u1.z + w1.w*u1.w;
        g_uhatb[(((size_t)b * NI + i) * 10 + j) * 16 + d] = __float2bfloat16(acc);
    }
}

__global__ __launch_bounds__(256)
void routing_s_kernel() {
    __shared__ float Vsh[160];
    __shared__ float ssh[160];
    int tid = threadIdx.x;
    int b = blockIdx.y;
    if (tid < 160) { Vsh[tid] = g_V[b * 160 + tid]; ssh[tid] = 0.f; }
    __syncthreads();
    int d = tid & 15, il = tid >> 4;
    float accj[10];
    #pragma unroll
    for (int j = 0; j < 10; j++) accj[j] = 0.f;
    const int per = NI / 32;
    int i0 = blockIdx.x * per;
    for (int i = i0 + il; i < i0 + per; i += 16) {
        const __nv_bfloat16* uh = g_uhatb + (((size_t)b * NI + i) * 10) * 16 + d;
        float uv[10], e[10];
        float m = -1e30f;
        #pragma unroll
        for (int j = 0; j < 10; j++) {
            uv[j] = __bfloat162float(uh[j * 16]);
            float l = uv[j] * Vsh[j * 16 + d];
            e[j] = l;
            m = fmaxf(m, l);
        }
        float se = 0.f;
        #pragma unroll
        for (int j = 0; j < 10; j++) { e[j] = __expf(e[j] - m); se += e[j]; }
        float inv = 1.f / se;
        #pragma unroll
        for (int j = 0; j < 10; j++) accj[j] += e[j] * inv * uv[j];
    }
    #pragma unroll
    for (int j = 0; j < 10; j++) atomicAdd(&ssh[j * 16 + d], accj[j]);
    __syncthreads();
    if (tid < 160) atomicAdd(&g_s[b * 160 + tid], ssh[tid]);
}

__global__ void v_update_kernel(int last, float* __restrict__ dout) {
    __shared__ float s2sh[10];
    __shared__ float nrm[10];
    __shared__ int amax;
    int b = blockIdx.x, tid = threadIdx.x;
    int j = tid >> 4, d = tid & 15;
    if (tid < 10) s2sh[tid] = 0.f;
    __syncthreads();
    float sv = g_s[b * 160 + tid];
    atomicAdd(&s2sh[j], sv * sv);
    __syncthreads();
    float s2 = s2sh[j];
    float v = s2 / (1.f + s2) * sv * rsqrtf(s2 + EPSQ);
    if (!last) {
        g_V[b * 160 + tid] += v;
    } else {
        if (d == 0) nrm[j] = s2 / (1.f + s2) * sqrtf(s2) * rsqrtf(s2 + EPSQ);
        __syncthreads();
        if (tid == 0) {
            int bm = 0; float mx = nrm[0];
            for (int jj = 1; jj < 10; jj++)
                if (nrm[jj] > mx) { mx = nrm[jj]; bm = jj; }
            amax = bm;
        }
        if (d == 0) dout[b * 10 + j] = nrm[j];
        __syncthreads();
        g_masked[b * 160 + tid] = (j == amax) ? v : 0.f;
    }
}

__global__ void fc_kernel(const float* __restrict__ in, const float* __restrict__ W,
                          const float* __restrict__ bias, float* __restrict__ out,
                          int IN, int OUT, int act) {
    int gid = blockIdx.x * blockDim.x + threadIdx.x;
    if (gid >= BATCH * OUT) return;
    int o = gid % OUT, b = gid / OUT;
    const float* ip = in + (size_t)b * IN;
    float acc = bias[o];
    for (int k = 0; k < IN; k++) acc += ip[k] * W[(size_t)k * OUT + o];
    if (act == 1) acc = fmaxf(acc, 0.f);
    else          acc = 1.f / (1.f + __expf(-acc));
    out[gid] = acc;
}

// ---------------- launch ----------------
extern "C" void kernel_launch(void* const* d_in, const int* in_sizes, int n_in,
                              void* d_out, int out_size) {
    const float* x   = (const float*)d_in[0];
    const float* c1w = (const float*)d_in[1];
    const float* c1b = (const float*)d_in[2];
    const float* c2w = (const float*)d_in[3];
    const float* c2b = (const float*)d_in[4];
    const float* pcw = (const float*)d_in[5];
    const float* pcb = (const float*)d_in[6];
    const float* Wc  = (const float*)d_in[7];
    const float* w1  = (const float*)d_in[8];
    const float* b1  = (const float*)d_in[9];
    const float* w2  = (const float*)d_in[10];
    const float* b2  = (const float*)d_in[11];
    const float* w3  = (const float*)d_in[12];
    const float* b3  = (const float*)d_in[13];
    float* dout = (float*)d_out;

    __nv_bfloat16 *p_c1b, *p_c2b, *p_w2h, *p_w2l, *p_wph, *p_wpl;
    float *p_part, *p_p, *p_s, *p_V, *p_masked, *p_d1, *p_d2;
    cudaGetSymbolAddress((void**)&p_c1b, g_c1b);
    cudaGetSymbolAddress((void**)&p_c2b, g_c2b);
    cudaGetSymbolAddress((void**)&p_part, g_part);
    cudaGetSymbolAddress((void**)&p_p,  g_p);
    cudaGetSymbolAddress((void**)&p_w2h, g_w2h);
    cudaGetSymbolAddress((void**)&p_w2l, g_w2l);
    cudaGetSymbolAddress((void**)&p_wph, g_wph);
    cudaGetSymbolAddress((void**)&p_wpl, g_wpl);
    cudaGetSymbolAddress((void**)&p_s,  g_s);
    cudaGetSymbolAddress((void**)&p_V,  g_V);
    cudaGetSymbolAddress((void**)&p_masked, g_masked);
    cudaGetSymbolAddress((void**)&p_d1, g_d1);
    cudaGetSymbolAddress((void**)&p_d2, g_d2);

    auto conv2 = conv_mma_kernel<56, 56, 52, 52, 5, 1, 100, 2, 43264>;
    auto convp = conv_mma_kernel<52, 52, 22, 22, 9, 2, 324, 12, 7744>;
    cudaFuncSetAttribute(conv2, cudaFuncAttributeMaxDynamicSharedMemorySize, SMEM_CONV_TOTAL);
    cudaFuncSetAttribute(convp, cudaFuncAttributeMaxDynamicSharedMemorySize, SMEM_CONV_TOTAL);

    transform_wsplit_kernel<<<(100 * 64 * 128 + 255) / 256, 256>>>(c2w, p_w2h, p_w2l, 5, 5, 100);
    transform_wsplit_kernel<<<(324 * 64 * 128 + 255) / 256, 256>>>(pcw, p_wph, p_wpl, 9, 9, 324);

    conv1_kernel<<<dim3(4, 8, 16), 196>>>(x, c1w, c1b, p_c1b);

    conv2<<<dim3(338, 2), 512, SMEM_CONV_TOTAL>>>(p_c1b, p_w2h, p_w2l, p_part);
    reduce2_kernel<<<(int)(((size_t)43264 * 128 + 255) / 256), 256>>>(p_part, c2b, p_c2b);

    convp<<<dim3(61, 12), 512, SMEM_CONV_TOTAL>>>(p_c2b, p_wph, p_wpl, p_part);
    reducep_kernel<<<(7744 * 64 + 255) / 256, 256>>>(p_part, pcb, p_p);

    squash_u_kernel<<<(BATCH * NI + 255) / 256, 256>>>();
    uhat_kernel<<<((size_t)NI * 160 + 255) / 256, 256>>>(Wc);

    cudaMemsetAsync(p_V, 0, BATCH * 160 * sizeof(float));
    for (int r = 0; r < 3; r++) {
        cudaMemsetAsync(p_s, 0, BATCH * 160 * sizeof(float));
        routing_s_kernel<<<dim3(32, 16), 256>>>();
        v_update_kernel<<<16, 160>>>(r == 2 ? 1 : 0, dout);
    }

    fc_kernel<<<(BATCH * 512 + 255) / 256, 256>>>(p_masked, w1, b1, p_d1, 160, 512, 1);
    fc_kernel<<<(BATCH * 1024 + 255) / 256, 256>>>(p_d1, w2, b2, p_d2, 512, 1024, 1);
    fc_kernel<<<(BATCH * 4096 + 255) / 256, 256>>>(p_d2, w3, b3, dout + 160, 1024, 4096, 2);
}

// round 12
// speedup vs baseline: 4.3944x; 1.3640x over previous
#include <cuda_runtime.h>
#include <cuda_bf16.h>
#include <cstdint>

#define EPSQ 1e-8f
static const int BATCH = 16;
static const int NI = 15488;

// ---------------- scratch ----------------
__device__ __nv_bfloat16 g_c1b[(size_t)50176 * 256];   // conv1 out, bf16 NHWC
__device__ __nv_bfloat16 g_c2b[(size_t)43264 * 256];
__device__ float g_part[(size_t)12 * 7744 * 256];      // split-K partials (conv2 uses 2*43264*256)
__device__ float g_p [(size_t)16 * 256 * 22 * 22];
__device__ float g_u [(size_t)16 * 15488 * 8];
__device__ __nv_bfloat16 g_uhatb[(size_t)16 * 15488 * 10 * 16];
__device__ __nv_bfloat16 g_w2b[(size_t)100 * 16384];   // [chunk][64k x 256n bf16 swizzled]
__device__ __nv_bfloat16 g_wpb[(size_t)324 * 16384];
__device__ float g_s[16 * 160];
__device__ float g_V[16 * 160];
__device__ float g_masked[16 * 160];
__device__ float g_d1[16 * 512];
__device__ float g_d2[16 * 1024];

// ---------------- helpers ----------------
__device__ __forceinline__ uint32_t smem_to_u32(const void* p) {
    uint32_t a;
    asm("{ .reg .u64 t; cvta.to.shared.u64 t, %1; cvt.u32.u64 %0, t; }" : "=r"(a) : "l"(p));
    return a;
}
__device__ __forceinline__ void ldsm_x4(uint32_t& r0, uint32_t& r1, uint32_t& r2, uint32_t& r3, uint32_t addr) {
    asm volatile("ldmatrix.sync.aligned.m8n8.x4.shared.b16 {%0,%1,%2,%3}, [%4];"
                 : "=r"(r0), "=r"(r1), "=r"(r2), "=r"(r3) : "r"(addr));
}
__device__ __forceinline__ void ldsm_x4_t(uint32_t& r0, uint32_t& r1, uint32_t& r2, uint32_t& r3, uint32_t addr) {
    asm volatile("ldmatrix.sync.aligned.m8n8.x4.trans.shared.b16 {%0,%1,%2,%3}, [%4];"
                 : "=r"(r0), "=r"(r1), "=r"(r2), "=r"(r3) : "r"(addr));
}
__device__ __forceinline__ void mma16816(float* c, const uint32_t* a, const uint32_t* b) {
    asm volatile("mma.sync.aligned.m16n8k16.row.col.f32.bf16.bf16.f32 "
                 "{%0,%1,%2,%3}, {%4,%5,%6,%7}, {%8,%9}, {%0,%1,%2,%3};"
                 : "+f"(c[0]), "+f"(c[1]), "+f"(c[2]), "+f"(c[3])
                 : "r"(a[0]), "r"(a[1]), "r"(a[2]), "r"(a[3]), "r"(b[0]), "r"(b[1]));
}
#define CP_ASYNC16(dst, src, sz) \
    asm volatile("cp.async.cg.shared.global [%0], [%1], 16, %2;" :: "r"(dst), "l"(src), "r"(sz))
#define CP_COMMIT() asm volatile("cp.async.commit_group;" ::: "memory")
#define CP_WAIT(n)  asm volatile("cp.async.wait_group %0;" :: "n"(n) : "memory")

// ---------------- weight transform: single bf16, [chunk][64k x 256n, 512B rows, XOR (k&7)<<4] ----------------
__global__ void transform_w_kernel(const float* __restrict__ w,
                                   __nv_bfloat16* __restrict__ wb,
                                   int KH, int KW, int NCHUNK) {
    int idx = blockIdx.x * 256 + threadIdx.x;
    int total = NCHUNK * 64 * 128;
    if (idx >= total) return;
    int np = idx & 127;
    int k  = (idx >> 7) & 63;
    int chunk = idx >> 13;
    int kyx = chunk >> 2;
    int ic = (chunk & 3) * 64 + k;
    int ky = kyx / KW, kx = kyx % KW;
    int oc = np * 2;
    size_t KHW = (size_t)KH * KW;
    size_t wi = (((size_t)oc * 256 + ic) * KH + ky) * KW + kx;
    ushort h0 = __bfloat16_as_ushort(__float2bfloat16(w[wi]));
    ushort h1 = __bfloat16_as_ushort(__float2bfloat16(w[wi + 256 * KHW]));
    int off = k * 512 + np * 4;
    int sw = off ^ ((k & 7) << 4);
    *(uint32_t*)((char*)wb + (size_t)chunk * 32768 + sw) = ((uint32_t)h1 << 16) | h0;
}

// ---------------- conv1: 1->256, 9x9, s1, NHWC bf16 out ----------------
__global__ __launch_bounds__(196)
void conv1_kernel(const float* __restrict__ x, const float* __restrict__ w,
                  const float* __restrict__ bias, __nv_bfloat16* __restrict__ ob16) {
    __shared__ float s_in[36 * 36];
    __shared__ float s_w[4 * 81];
    int tid = threadIdx.x;
    int tileY = blockIdx.x >> 1, tileX = blockIdx.x & 1;
    int b = blockIdx.z;
    int ocg = blockIdx.y;
    for (int idx = tid; idx < 1296; idx += 196) {
        int r = idx / 36, cc = idx % 36;
        s_in[idx] = x[((size_t)b * 64 + tileY * 28 + r) * 64 + tileX * 28 + cc];
    }
    int sy = tid / 14, sx = tid % 14;
    for (int oi = 0; oi < 32; oi += 4) {
        __syncthreads();
        for (int idx = tid; idx < 4 * 81; idx += 196) {
            int o = idx / 81, k = idx % 81;
            s_w[idx] = w[(size_t)(ocg * 32 + oi + o) * 81 + k];
        }
        __syncthreads();
        float acc[2][2][4];
        #pragma unroll
        for (int a = 0; a < 2; a++)
            #pragma unroll
            for (int q = 0; q < 2; q++)
                #pragma unroll
                for (int o = 0; o < 4; o++) acc[a][q][o] = 0.f;
        for (int ky = 0; ky < 9; ky++) {
            #pragma unroll
            for (int kx = 0; kx < 9; kx++) {
                int k = ky * 9 + kx;
                float w0 = s_w[k], w1 = s_w[81 + k], w2 = s_w[162 + k], w3 = s_w[243 + k];
                #pragma unroll
                for (int a = 0; a < 2; a++)
                    #pragma unroll
                    for (int q = 0; q < 2; q++) {
                        float v = s_in[(sy + 14 * a + ky) * 36 + sx + 14 * q + kx];
                        acc[a][q][0] += v * w0; acc[a][q][1] += v * w1;
                        acc[a][q][2] += v * w2; acc[a][q][3] += v * w3;
                    }
            }
        }
        int oc = ocg * 32 + oi;
        float b0 = bias[oc], b1 = bias[oc + 1], b2 = bias[oc + 2], b3 = bias[oc + 3];
        #pragma unroll
        for (int a = 0; a < 2; a++)
            #pragma unroll
            for (int q = 0; q < 2; q++) {
                int oy = tileY * 28 + a * 14 + sy;
                int ox = tileX * 28 + q * 14 + sx;
                size_t ob = ((size_t)(b * 56 + oy) * 56 + ox) * 256 + oc;
                ushort h0 = __bfloat16_as_ushort(__float2bfloat16(fmaxf(acc[a][q][0] + b0, 0.f)));
                ushort h1 = __bfloat16_as_ushort(__float2bfloat16(fmaxf(acc[a][q][1] + b1, 0.f)));
                ushort h2 = __bfloat16_as_ushort(__float2bfloat16(fmaxf(acc[a][q][2] + b2, 0.f)));
                ushort h3 = __bfloat16_as_ushort(__float2bfloat16(fmaxf(acc[a][q][3] + b3, 0.f)));
                *(uint2*)(ob16 + ob) = make_uint2(((uint32_t)h1 << 16) | h0,
                                                  ((uint32_t)h3 << 16) | h2);
            }
    }
}

// ---------------- HMMA implicit-GEMM conv, single bf16, 3-stage cp.async, one sync/chunk ----------------
// Block 512 thr (16 warps 4Mx4N); tile M=128 pos x N=256 oc; warp 32x64.
// Stage 48KB: A 16K | B 32K. 3 stages = 144KB.
#define STG_STRIDE 49152
#define SMEM_CONV_TOTAL (3 * STG_STRIDE)

template<int IH, int IW, int OH, int OW, int KW, int STRIDE, int NCHUNK, int KSPLIT, int NPOS>
__global__ __launch_bounds__(512, 1)
void conv_mma_kernel(const __nv_bfloat16* __restrict__ inb,
                     const __nv_bfloat16* __restrict__ wb,
                     float* __restrict__ part) {
    extern __shared__ char smem[];
    const uint32_t sb = smem_to_u32(smem);
    const int tid = threadIdx.x;
    const int wid = tid >> 5, lid = tid & 31;
    const int tile = blockIdx.x;

    const int r = tid >> 2, sp = tid & 3;    // A fill: 4 thr/row, 2x16B each
    const int p_mine = tile * 128 + r;
    const bool pvalid = p_mine < NPOS;
    int pb = 0, pr = 0, pcx = 0;
    if (pvalid) {
        pb = p_mine / (OH * OW);
        int rem = p_mine - pb * (OH * OW);
        pr = rem / OW;
        pcx = rem - pr * OW;
    }
    const int asz = pvalid ? 16 : 0;

    const int wm = wid >> 2, wn = wid & 3;
    const int lane15 = lid & 15, lane16 = lid >> 4;
    const int gid = lid >> 2, tig = lid & 3;

    float acc[2][8][4];
    #pragma unroll
    for (int ma = 0; ma < 2; ma++)
        #pragma unroll
        for (int na = 0; na < 8; na++)
            #pragma unroll
            for (int q = 0; q < 4; q++) acc[ma][na][q] = 0.f;

    const int NC = NCHUNK / KSPLIT;
    const int coff = blockIdx.y * NC;

    auto fill = [&](int stage, int chunk) {
        uint32_t s0 = sb + stage * STG_STRIDE;
        // B: copy pre-swizzled 32KB
        const char* bsrc = (const char*)(wb + (size_t)chunk * 16384);
        #pragma unroll
        for (int i = 0; i < 4; i++) {
            uint32_t u = (tid + i * 512) * 16;
            CP_ASYNC16(s0 + 16384 + u, bsrc + u, 16);
        }
        // A: gather NHWC bf16 rows (64 ch = 128B)
        const int kyx = chunk >> 2;
        const int ic0 = (chunk & 3) * 64;
        const int ky = kyx / KW, kx = kyx % KW;
        size_t srcbase = 0;
        if (pvalid) {
            int iy = pr * STRIDE + ky, ix = pcx * STRIDE + kx;
            srcbase = (((size_t)pb * IH + iy) * IW + ix) * 256 + ic0;
        }
        #pragma unroll
        for (int q = 0; q < 2; q++) {
            int seg = sp * 2 + q;
            uint32_t off = r * 128 + seg * 16;
            uint32_t sw = off ^ ((r & 7) << 4);
            CP_ASYNC16(s0 + sw, (const char*)(inb + srcbase + seg * 8), asz);
        }
    };

    fill(0, coff);              CP_COMMIT();
    if (NC > 1) { fill(1, coff + 1); CP_COMMIT(); }

    int st = 0;
    for (int i = 0; i < NC; ++i) {
        if (i + 1 < NC) { CP_WAIT(1); } else { CP_WAIT(0); }  // group i drained
        __syncthreads();   // also: stage (i+2)%3 was last read in compute(i-1)
        if (i + 2 < NC) { fill((st + 2) % 3, coff + i + 2); CP_COMMIT(); }

        const uint32_t s0 = sb + st * STG_STRIDE;
        #pragma unroll
        for (int ks = 0; ks < 4; ks++) {
            uint32_t B[8][2];
            const int brow = ks * 16 + lane15;
            #pragma unroll
            for (int q = 0; q < 4; q++) {
                uint32_t off = brow * 512 + wn * 128 + q * 32 + lane16 * 16;
                uint32_t sw = off ^ ((brow & 7) << 4);
                ldsm_x4_t(B[2*q][0], B[2*q][1], B[2*q+1][0], B[2*q+1][1], s0 + 16384 + sw);
            }
            #pragma unroll
            for (int ma = 0; ma < 2; ma++) {
                const int arow = wm * 32 + ma * 16 + lane15;
                uint32_t offA = arow * 128 + ks * 32 + lane16 * 16;
                uint32_t swA = offA ^ ((arow & 7) << 4);
                uint32_t a[4];
                ldsm_x4(a[0], a[1], a[2], a[3], s0 + swA);
                #pragma unroll
                for (int na = 0; na < 8; na++) mma16816(acc[ma][na], a, B[na]);
            }
        }
        st = (st + 1) % 3;
    }

    float* op0 = part + (size_t)blockIdx.y * NPOS * 256;
    #pragma unroll
    for (int ma = 0; ma < 2; ma++)
        #pragma unroll
        for (int h = 0; h < 2; h++) {
            int p = tile * 128 + wm * 32 + ma * 16 + h * 8 + gid;
            if (p >= NPOS) continue;
            float* op = op0 + (size_t)p * 256 + wn * 64 + tig * 2;
            #pragma unroll
            for (int na = 0; na < 8; na++)
                *(float2*)(op + na * 8) = make_float2(acc[ma][na][h * 2], acc[ma][na][h * 2 + 1]);
        }
}

// ---------------- reduce conv2 (2-way) -> bias+relu -> bf16 NHWC ----------------
__global__ void reduce2_kernel(const float* __restrict__ part, const float* __restrict__ bias,
                               __nv_bfloat16* __restrict__ ob16) {
    size_t gid = (size_t)blockIdx.x * 256 + threadIdx.x;
    if (gid >= (size_t)43264 * 128) return;
    int p = (int)(gid >> 7);
    int oc = ((int)gid & 127) * 2;
    const float* p0 = part + (size_t)p * 256 + oc;
    const size_t half = (size_t)43264 * 256;
    float v0 = fmaxf(p0[0] + p0[half]     + bias[oc],     0.f);
    float v1 = fmaxf(p0[1] + p0[half + 1] + bias[oc + 1], 0.f);
    uint32_t w = ((uint32_t)__bfloat16_as_ushort(__float2bfloat16(v1)) << 16)
               | __bfloat16_as_ushort(__float2bfloat16(v0));
    *(uint32_t*)(ob16 + (size_t)p * 256 + oc) = w;
}

// ---------------- reduce pc partials (12-way) -> bias -> fp32 NCHW ----------------
__global__ void reducep_kernel(const float* __restrict__ part, const float* __restrict__ bias,
                               float* __restrict__ out) {
    int gid = blockIdx.x * 256 + threadIdx.x;
    if (gid >= 7744 * 64) return;
    int p = gid >> 6, oc = (gid & 63) * 4;
    const size_t seg = (size_t)7744 * 256;
    const float* p0 = part + (size_t)p * 256 + oc;
    float4 v = *(const float4*)p0;
    #pragma unroll
    for (int k = 1; k < 12; k++) {
        float4 t = *(const float4*)(p0 + k * seg);
        v.x += t.x; v.y += t.y; v.z += t.z; v.w += t.w;
    }
    const float4 bv = *(const float4*)(bias + oc);
    v.x += bv.x; v.y += bv.y; v.z += bv.z; v.w += bv.w;
    int b = p / 484;
    int rem = p - b * 484;
    int rr = rem / 22, cx = rem - rr * 22;
    size_t base = (((size_t)b * 256 + oc) * 22 + rr) * 22 + cx;
    out[base] = v.x; out[base + 484] = v.y;
    out[base + 2 * 484] = v.z; out[base + 3 * 484] = v.w;
}

// ---------------- squash / u_hat / routing / v_update / fc ----------------
__global__ void squash_u_kernel() {
    int cap = blockIdx.x * 256 + threadIdx.x;
    if (cap >= BATCH * NI) return;
    const float4* pp = (const float4*)(g_p + (size_t)cap * 8);
    float4 a = pp[0], c = pp[1];
    float s2 = a.x*a.x + a.y*a.y + a.z*a.z + a.w*a.w + c.x*c.x + c.y*c.y + c.z*c.z + c.w*c.w;
    float f = s2 / (1.f + s2) * rsqrtf(s2 + EPSQ);
    a.x *= f; a.y *= f; a.z *= f; a.w *= f;
    c.x *= f; c.y *= f; c.z *= f; c.w *= f;
    float4* uo = (float4*)(g_u + (size_t)cap * 8);
    uo[0] = a; uo[1] = c;
}

__global__ __launch_bounds__(256)
void uhat_kernel(const float* __restrict__ W) {
    int gid = blockIdx.x * 256 + threadIdx.x;
    int d = gid & 15;
    int j = (gid >> 4) % 10;
    int i = gid / 160;
    if (i >= NI) return;
    const float4* Wp = (const float4*)(W + (((size_t)j * NI + i) * 16 + d) * 8);
    float4 w0 = Wp[0], w1 = Wp[1];
    for (int b = 0; b < BATCH; b++) {
        const float4* up = (const float4*)(g_u + ((size_t)b * NI + i) * 8);
        float4 u0 = up[0], u1 = up[1];
        float acc = w0.x*u0.x + w0.y*u0.y + w0.z*u0.z + w0.w*u0.w
                  + w1.x*u1.x + w1.y*u1.y + w1.z*u1.z + w1.w*u1.w;
        g_uhatb[(((size_t)b * NI + i) * 10 + j) * 16 + d] = __float2bfloat16(acc);
    }
}

__global__ __launch_bounds__(256)
void routing_s_kernel() {
    __shared__ float Vsh[160];
    __shared__ float ssh[160];
    int tid = threadIdx.x;
    int b = blockIdx.y;
    if (tid < 160) { Vsh[tid] = g_V[b * 160 + tid]; ssh[tid] = 0.f; }
    __syncthreads();
    int d = tid & 15, il = tid >> 4;
    float accj[10];
    #pragma unroll
    for (int j = 0; j < 10; j++) accj[j] = 0.f;
    const int per = NI / 32;
    int i0 = blockIdx.x * per;
    for (int i = i0 + il; i < i0 + per; i += 16) {
        const __nv_bfloat16* uh = g_uhatb + (((size_t)b * NI + i) * 10) * 16 + d;
        float uv[10], e[10];
        float m = -1e30f;
        #pragma unroll
        for (int j = 0; j < 10; j++) {
            uv[j] = __bfloat162float(uh[j * 16]);
            float l = uv[j] * Vsh[j * 16 + d];
            e[j] = l;
            m = fmaxf(m, l);
        }
        float se = 0.f;
        #pragma unroll
        for (int j = 0; j < 10; j++) { e[j] = __expf(e[j] - m); se += e[j]; }
        float inv = 1.f / se;
        #pragma unroll
        for (int j = 0; j < 10; j++) accj[j] += e[j] * inv * uv[j];
    }
    #pragma unroll
    for (int j = 0; j < 10; j++) atomicAdd(&ssh[j * 16 + d], accj[j]);
    __syncthreads();
    if (tid < 160) atomicAdd(&g_s[b * 160 + tid], ssh[tid]);
}

__global__ void v_update_kernel(int last, float* __restrict__ dout) {
    __shared__ float s2sh[10];
    __shared__ float nrm[10];
    __shared__ int amax;
    int b = blockIdx.x, tid = threadIdx.x;
    int j = tid >> 4, d = tid & 15;
    if (tid < 10) s2sh[tid] = 0.f;
    __syncthreads();
    float sv = g_s[b * 160 + tid];
    atomicAdd(&s2sh[j], sv * sv);
    __syncthreads();
    float s2 = s2sh[j];
    float v = s2 / (1.f + s2) * sv * rsqrtf(s2 + EPSQ);
    if (!last) {
        g_V[b * 160 + tid] += v;
    } else {
        if (d == 0) nrm[j] = s2 / (1.f + s2) * sqrtf(s2) * rsqrtf(s2 + EPSQ);
        __syncthreads();
        if (tid == 0) {
            int bm = 0; float mx = nrm[0];
            for (int jj = 1; jj < 10; jj++)
                if (nrm[jj] > mx) { mx = nrm[jj]; bm = jj; }
            amax = bm;
        }
        if (d == 0) dout[b * 10 + j] = nrm[j];
        __syncthreads();
        g_masked[b * 160 + tid] = (j == amax) ? v : 0.f;
    }
}

__global__ void fc_kernel(const float* __restrict__ in, const float* __restrict__ W,
                          const float* __restrict__ bias, float* __restrict__ out,
                          int IN, int OUT, int act) {
    int gid = blockIdx.x * blockDim.x + threadIdx.x;
    if (gid >= BATCH * OUT) return;
    int o = gid % OUT, b = gid / OUT;
    const float* ip = in + (size_t)b * IN;
    float acc = bias[o];
    for (int k = 0; k < IN; k++) acc += ip[k] * W[(size_t)k * OUT + o];
    if (act == 1) acc = fmaxf(acc, 0.f);
    else          acc = 1.f / (1.f + __expf(-acc));
    out[gid] = acc;
}

// ---------------- launch ----------------
extern "C" void kernel_launch(void* const* d_in, const int* in_sizes, int n_in,
                              void* d_out, int out_size) {
    const float* x   = (const float*)d_in[0];
    const float* c1w = (const float*)d_in[1];
    const float* c1b = (const float*)d_in[2];
    const float* c2w = (const float*)d_in[3];
    const float* c2b = (const float*)d_in[4];
    const float* pcw = (const float*)d_in[5];
    const float* pcb = (const float*)d_in[6];
    const float* Wc  = (const float*)d_in[7];
    const float* w1  = (const float*)d_in[8];
    const float* b1  = (const float*)d_in[9];
    const float* w2  = (const float*)d_in[10];
    const float* b2  = (const float*)d_in[11];
    const float* w3  = (const float*)d_in[12];
    const float* b3  = (const float*)d_in[13];
    float* dout = (float*)d_out;

    __nv_bfloat16 *p_c1b, *p_c2b, *p_w2b, *p_wpb;
    float *p_part, *p_p, *p_s, *p_V, *p_masked, *p_d1, *p_d2;
    cudaGetSymbolAddress((void**)&p_c1b, g_c1b);
    cudaGetSymbolAddress((void**)&p_c2b, g_c2b);
    cudaGetSymbolAddress((void**)&p_part, g_part);
    cudaGetSymbolAddress((void**)&p_p,  g_p);
    cudaGetSymbolAddress((void**)&p_w2b, g_w2b);
    cudaGetSymbolAddress((void**)&p_wpb, g_wpb);
    cudaGetSymbolAddress((void**)&p_s,  g_s);
    cudaGetSymbolAddress((void**)&p_V,  g_V);
    cudaGetSymbolAddress((void**)&p_masked, g_masked);
    cudaGetSymbolAddress((void**)&p_d1, g_d1);
    cudaGetSymbolAddress((void**)&p_d2, g_d2);

    auto conv2 = conv_mma_kernel<56, 56, 52, 52, 5, 1, 100, 2, 43264>;
    auto convp = conv_mma_kernel<52, 52, 22, 22, 9, 2, 324, 12, 7744>;
    cudaFuncSetAttribute(conv2, cudaFuncAttributeMaxDynamicSharedMemorySize, SMEM_CONV_TOTAL);
    cudaFuncSetAttribute(convp, cudaFuncAttributeMaxDynamicSharedMemorySize, SMEM_CONV_TOTAL);

    transform_w_kernel<<<(100 * 64 * 128 + 255) / 256, 256>>>(c2w, p_w2b, 5, 5, 100);
    transform_w_kernel<<<(324 * 64 * 128 + 255) / 256, 256>>>(pcw, p_wpb, 9, 9, 324);

    conv1_kernel<<<dim3(4, 8, 16), 196>>>(x, c1w, c1b, p_c1b);

    conv2<<<dim3(338, 2), 512, SMEM_CONV_TOTAL>>>(p_c1b, p_w2b, p_part);
    reduce2_kernel<<<(int)(((size_t)43264 * 128 + 255) / 256), 256>>>(p_part, c2b, p_c2b);

    convp<<<dim3(61, 12), 512, SMEM_CONV_TOTAL>>>(p_c2b, p_wpb, p_part);
    reducep_kernel<<<(7744 * 64 + 255) / 256, 256>>>(p_part, pcb, p_p);

    squash_u_kernel<<<(BATCH * NI + 255) / 256, 256>>>();
    uhat_kernel<<<((size_t)NI * 160 + 255) / 256, 256>>>(Wc);

    cudaMemsetAsync(p_V, 0, BATCH * 160 * sizeof(float));
    for (int r = 0; r < 3; r++) {
        cudaMemsetAsync(p_s, 0, BATCH * 160 * sizeof(float));
        routing_s_kernel<<<dim3(32, 16), 256>>>();
        v_update_kernel<<<16, 160>>>(r == 2 ? 1 : 0, dout);
    }

    fc_kernel<<<(BATCH * 512 + 255) / 256, 256>>>(p_masked, w1, b1, p_d1, 160, 512, 1);
    fc_kernel<<<(BATCH * 1024 + 255) / 256, 256>>>(p_d1, w2, b2, p_d2, 512, 1024, 1);
    fc_kernel<<<(BATCH * 4096 + 255) / 256, 256>>>(p_d2, w3, b3, dout + 160, 1024, 4096, 2);
}

// round 13
// speedup vs baseline: 4.8620x; 1.1064x over previous
#include <cuda_runtime.h>
#include <cuda_bf16.h>
#include <cstdint>

#define EPSQ 1e-8f
static const int BATCH = 16;
static const int NI = 15488;

// ---------------- scratch ----------------
__device__ __nv_bfloat16 g_c1b[(size_t)50176 * 256];   // conv1 out, bf16 NHWC
__device__ __nv_bfloat16 g_c2b[(size_t)43264 * 256];
__device__ float g_part[(size_t)12 * 7744 * 256];      // split-K partials
__device__ float g_p [(size_t)16 * 256 * 22 * 22];
__device__ float g_u [(size_t)16 * 15488 * 8];
__device__ __nv_bfloat16 g_uhatb[(size_t)16 * 15488 * 10 * 16];
__device__ __nv_bfloat16 g_w1b[(size_t)2 * 16384];     // conv1 weights [chunk][64k x 256n swz], k>=81 zero
__device__ __nv_bfloat16 g_w2b[(size_t)100 * 16384];
__device__ __nv_bfloat16 g_wpb[(size_t)324 * 16384];
__device__ float g_s[16 * 160];
__device__ float g_V[16 * 160];
__device__ float g_masked[16 * 160];
__device__ float g_d1[16 * 512];
__device__ float g_d2[16 * 1024];

// ---------------- helpers ----------------
__device__ __forceinline__ uint32_t smem_to_u32(const void* p) {
    uint32_t a;
    asm("{ .reg .u64 t; cvta.to.shared.u64 t, %1; cvt.u32.u64 %0, t; }" : "=r"(a) : "l"(p));
    return a;
}
__device__ __forceinline__ void ldsm_x4(uint32_t& r0, uint32_t& r1, uint32_t& r2, uint32_t& r3, uint32_t addr) {
    asm volatile("ldmatrix.sync.aligned.m8n8.x4.shared.b16 {%0,%1,%2,%3}, [%4];"
                 : "=r"(r0), "=r"(r1), "=r"(r2), "=r"(r3) : "r"(addr));
}
__device__ __forceinline__ void ldsm_x4_t(uint32_t& r0, uint32_t& r1, uint32_t& r2, uint32_t& r3, uint32_t addr) {
    asm volatile("ldmatrix.sync.aligned.m8n8.x4.trans.shared.b16 {%0,%1,%2,%3}, [%4];"
                 : "=r"(r0), "=r"(r1), "=r"(r2), "=r"(r3) : "r"(addr));
}
__device__ __forceinline__ void mma16816(float* c, const uint32_t* a, const uint32_t* b) {
    asm volatile("mma.sync.aligned.m16n8k16.row.col.f32.bf16.bf16.f32 "
                 "{%0,%1,%2,%3}, {%4,%5,%6,%7}, {%8,%9}, {%0,%1,%2,%3};"
                 : "+f"(c[0]), "+f"(c[1]), "+f"(c[2]), "+f"(c[3])
                 : "r"(a[0]), "r"(a[1]), "r"(a[2]), "r"(a[3]), "r"(b[0]), "r"(b[1]));
}
#define CP_ASYNC16(dst, src, sz) \
    asm volatile("cp.async.cg.shared.global [%0], [%1], 16, %2;" :: "r"(dst), "l"(src), "r"(sz))
#define CP_COMMIT() asm volatile("cp.async.commit_group;" ::: "memory")
#define CP_WAIT(n)  asm volatile("cp.async.wait_group %0;" :: "n"(n) : "memory")

// ---------------- weight transforms ----------------
__global__ void transform_w_kernel(const float* __restrict__ w,
                                   __nv_bfloat16* __restrict__ wb,
                                   int KH, int KW, int NCHUNK) {
    int idx = blockIdx.x * 256 + threadIdx.x;
    int total = NCHUNK * 64 * 128;
    if (idx >= total) return;
    int np = idx & 127;
    int k  = (idx >> 7) & 63;
    int chunk = idx >> 13;
    int kyx = chunk >> 2;
    int ic = (chunk & 3) * 64 + k;
    int ky = kyx / KW, kx = kyx % KW;
    int oc = np * 2;
    size_t KHW = (size_t)KH * KW;
    size_t wi = (((size_t)oc * 256 + ic) * KH + ky) * KW + kx;
    ushort h0 = __bfloat16_as_ushort(__float2bfloat16(w[wi]));
    ushort h1 = __bfloat16_as_ushort(__float2bfloat16(w[wi + 256 * KHW]));
    int off = k * 512 + np * 4;
    int sw = off ^ ((k & 7) << 4);
    *(uint32_t*)((char*)wb + (size_t)chunk * 32768 + sw) = ((uint32_t)h1 << 16) | h0;
}

// conv1 weights (256,1,9,9): [chunk(2)][64k x 256n], k>=81 -> 0
__global__ void transform_w1_kernel(const float* __restrict__ w,
                                    __nv_bfloat16* __restrict__ wb) {
    int idx = blockIdx.x * 256 + threadIdx.x;
    if (idx >= 2 * 64 * 128) return;
    int np = idx & 127;
    int k  = (idx >> 7) & 63;
    int chunk = idx >> 13;
    int kk = chunk * 64 + k;
    int oc = np * 2;
    float f0 = (kk < 81) ? w[(size_t)oc * 81 + kk] : 0.f;
    float f1 = (kk < 81) ? w[(size_t)(oc + 1) * 81 + kk] : 0.f;
    ushort h0 = __bfloat16_as_ushort(__float2bfloat16(f0));
    ushort h1 = __bfloat16_as_ushort(__float2bfloat16(f1));
    int off = k * 512 + np * 4;
    int sw = off ^ ((k & 7) << 4);
    *(uint32_t*)((char*)wb + (size_t)chunk * 32768 + sw) = ((uint32_t)h1 << 16) | h0;
}

// ---------------- conv1 via HMMA: M=50176 pos, N=256, K=81 (pad 128) ----------------
// Same 128x256 tile / 16-warp layout as conv_mma. Both chunks resident; fused epilogue.
#define C1_STG 49152
#define C1_SMEM (2 * C1_STG)

__global__ __launch_bounds__(512, 1)
void conv1_mma_kernel(const float* __restrict__ x,
                      const __nv_bfloat16* __restrict__ wb,
                      const float* __restrict__ bias,
                      __nv_bfloat16* __restrict__ ob16) {
    extern __shared__ char smem[];
    const uint32_t sb = smem_to_u32(smem);
    const int tid = threadIdx.x;
    const int wid = tid >> 5, lid = tid & 31;
    const int tile = blockIdx.x;

    const int r = tid >> 2, sp = tid & 3;
    const int p_mine = tile * 128 + r;
    const bool pvalid = p_mine < 50176;
    int pb = 0, pr = 0, pcx = 0;
    if (pvalid) {
        pb = p_mine / 3136;
        int rem = p_mine - pb * 3136;
        pr = rem / 56;
        pcx = rem - pr * 56;
    }

    const int wm = wid >> 2, wn = wid & 3;
    const int lane15 = lid & 15, lane16 = lid >> 4;
    const int gid = lid >> 2, tig = lid & 3;

    float acc[2][8][4];
    #pragma unroll
    for (int ma = 0; ma < 2; ma++)
        #pragma unroll
        for (int na = 0; na < 8; na++)
            #pragma unroll
            for (int q = 0; q < 4; q++) acc[ma][na][q] = 0.f;

    // fill both stages: B via cp.async, A via im2col gather + STS
    #pragma unroll
    for (int c = 0; c < 2; c++) {
        uint32_t s0 = sb + c * C1_STG;
        const char* bsrc = (const char*)(wb + (size_t)c * 16384);
        #pragma unroll
        for (int i = 0; i < 4; i++) {
            uint32_t u = (tid + i * 512) * 16;
            CP_ASYNC16(s0 + 16384 + u, bsrc + u, 16);
        }
        const float* xb = x + (size_t)pb * 4096;
        #pragma unroll
        for (int t = 0; t < 8; t++) {
            int k0 = c * 64 + sp * 16 + 2 * t;
            float v0 = 0.f, v1 = 0.f;
            if (pvalid && k0 < 81) {
                int ky = k0 / 9, kx = k0 - 9 * ky;
                v0 = xb[(pr + ky) * 64 + pcx + kx];
            }
            if (pvalid && k0 + 1 < 81) {
                int ky = (k0 + 1) / 9, kx = (k0 + 1) - 9 * ky;
                v1 = xb[(pr + ky) * 64 + pcx + kx];
            }
            uint32_t pk = ((uint32_t)__bfloat16_as_ushort(__float2bfloat16(v1)) << 16)
                        | __bfloat16_as_ushort(__float2bfloat16(v0));
            uint32_t off = r * 128 + (sp * 16 + 2 * t) * 2;
            uint32_t sw = off ^ ((r & 7) << 4);
            *(uint32_t*)(smem + c * C1_STG + sw) = pk;
        }
    }
    CP_COMMIT();
    CP_WAIT(0);
    __syncthreads();

    #pragma unroll
    for (int c = 0; c < 2; c++) {
        const uint32_t s0 = sb + c * C1_STG;
        #pragma unroll
        for (int ks = 0; ks < 4; ks++) {
            uint32_t B[8][2];
            const int brow = ks * 16 + lane15;
            #pragma unroll
            for (int q = 0; q < 4; q++) {
                uint32_t off = brow * 512 + wn * 128 + q * 32 + lane16 * 16;
                uint32_t sw = off ^ ((brow & 7) << 4);
                ldsm_x4_t(B[2*q][0], B[2*q][1], B[2*q+1][0], B[2*q+1][1], s0 + 16384 + sw);
            }
            #pragma unroll
            for (int ma = 0; ma < 2; ma++) {
                const int arow = wm * 32 + ma * 16 + lane15;
                uint32_t offA = arow * 128 + ks * 32 + lane16 * 16;
                uint32_t swA = offA ^ ((arow & 7) << 4);
                uint32_t a[4];
                ldsm_x4(a[0], a[1], a[2], a[3], s0 + swA);
                #pragma unroll
                for (int na = 0; na < 8; na++) mma16816(acc[ma][na], a, B[na]);
            }
        }
    }

    // fused epilogue: bias + relu -> bf16 NHWC
    #pragma unroll
    for (int ma = 0; ma < 2; ma++)
        #pragma unroll
        for (int h = 0; h < 2; h++) {
            int p = tile * 128 + wm * 32 + ma * 16 + h * 8 + gid;
            if (p >= 50176) continue;
            __nv_bfloat16* op = ob16 + (size_t)p * 256;
            #pragma unroll
            for (int na = 0; na < 8; na++) {
                int oc = wn * 64 + na * 8 + tig * 2;
                float v0 = fmaxf(acc[ma][na][h * 2 + 0] + bias[oc],     0.f);
                float v1 = fmaxf(acc[ma][na][h * 2 + 1] + bias[oc + 1], 0.f);
                uint32_t w = ((uint32_t)__bfloat16_as_ushort(__float2bfloat16(v1)) << 16)
                           | __bfloat16_as_ushort(__float2bfloat16(v0));
                *(uint32_t*)(op + oc) = w;
            }
        }
}

// ---------------- HMMA implicit-GEMM conv (conv2/pc), 3-stage cp.async ----------------
#define STG_STRIDE 49152
#define SMEM_CONV_TOTAL (3 * STG_STRIDE)

template<int IH, int IW, int OH, int OW, int KW, int STRIDE, int NCHUNK, int KSPLIT, int NPOS>
__global__ __launch_bounds__(512, 1)
void conv_mma_kernel(const __nv_bfloat16* __restrict__ inb,
                     const __nv_bfloat16* __restrict__ wb,
                     float* __restrict__ part) {
    extern __shared__ char smem[];
    const uint32_t sb = smem_to_u32(smem);
    const int tid = threadIdx.x;
    const int wid = tid >> 5, lid = tid & 31;
    const int tile = blockIdx.x;

    const int r = tid >> 2, sp = tid & 3;
    const int p_mine = tile * 128 + r;
    const bool pvalid = p_mine < NPOS;
    int pb = 0, pr = 0, pcx = 0;
    if (pvalid) {
        pb = p_mine / (OH * OW);
        int rem = p_mine - pb * (OH * OW);
        pr = rem / OW;
        pcx = rem - pr * OW;
    }
    const int asz = pvalid ? 16 : 0;

    const int wm = wid >> 2, wn = wid & 3;
    const int lane15 = lid & 15, lane16 = lid >> 4;
    const int gid = lid >> 2, tig = lid & 3;

    float acc[2][8][4];
    #pragma unroll
    for (int ma = 0; ma < 2; ma++)
        #pragma unroll
        for (int na = 0; na < 8; na++)
            #pragma unroll
            for (int q = 0; q < 4; q++) acc[ma][na][q] = 0.f;

    const int NC = NCHUNK / KSPLIT;
    const int coff = blockIdx.y * NC;

    auto fill = [&](int stage, int chunk) {
        uint32_t s0 = sb + stage * STG_STRIDE;
        const char* bsrc = (const char*)(wb + (size_t)chunk * 16384);
        #pragma unroll
        for (int i = 0; i < 4; i++) {
            uint32_t u = (tid + i * 512) * 16;
            CP_ASYNC16(s0 + 16384 + u, bsrc + u, 16);
        }
        const int kyx = chunk >> 2;
        const int ic0 = (chunk & 3) * 64;
        const int ky = kyx / KW, kx = kyx % KW;
        size_t srcbase = 0;
        if (pvalid) {
            int iy = pr * STRIDE + ky, ix = pcx * STRIDE + kx;
            srcbase = (((size_t)pb * IH + iy) * IW + ix) * 256 + ic0;
        }
        #pragma unroll
        for (int q = 0; q < 2; q++) {
            int seg = sp * 2 + q;
            uint32_t off = r * 128 + seg * 16;
            uint32_t sw = off ^ ((r & 7) << 4);
            CP_ASYNC16(s0 + sw, (const char*)(inb + srcbase + seg * 8), asz);
        }
    };

    fill(0, coff);              CP_COMMIT();
    if (NC > 1) { fill(1, coff + 1); CP_COMMIT(); }

    int st = 0;
    for (int i = 0; i < NC; ++i) {
        if (i + 1 < NC) { CP_WAIT(1); } else { CP_WAIT(0); }
        __syncthreads();
        if (i + 2 < NC) { fill((st + 2) % 3, coff + i + 2); CP_COMMIT(); }

        const uint32_t s0 = sb + st * STG_STRIDE;
        #pragma unroll
        for (int ks = 0; ks < 4; ks++) {
            uint32_t B[8][2];
            const int brow = ks * 16 + lane15;
            #pragma unroll
            for (int q = 0; q < 4; q++) {
                uint32_t off = brow * 512 + wn * 128 + q * 32 + lane16 * 16;
                uint32_t sw = off ^ ((brow & 7) << 4);
                ldsm_x4_t(B[2*q][0], B[2*q][1], B[2*q+1][0], B[2*q+1][1], s0 + 16384 + sw);
            }
            #pragma unroll
            for (int ma = 0; ma < 2; ma++) {
                const int arow = wm * 32 + ma * 16 + lane15;
                uint32_t offA = arow * 128 + ks * 32 + lane16 * 16;
                uint32_t swA = offA ^ ((arow & 7) << 4);
                uint32_t a[4];
                ldsm_x4(a[0], a[1], a[2], a[3], s0 + swA);
                #pragma unroll
                for (int na = 0; na < 8; na++) mma16816(acc[ma][na], a, B[na]);
            }
        }
        st = (st + 1) % 3;
    }

    float* op0 = part + (size_t)blockIdx.y * NPOS * 256;
    #pragma unroll
    for (int ma = 0; ma < 2; ma++)
        #pragma unroll
        for (int h = 0; h < 2; h++) {
            int p = tile * 128 + wm * 32 + ma * 16 + h * 8 + gid;
            if (p >= NPOS) continue;
            float* op = op0 + (size_t)p * 256 + wn * 64 + tig * 2;
            #pragma unroll
            for (int na = 0; na < 8; na++)
                *(float2*)(op + na * 8) = make_float2(acc[ma][na][h * 2], acc[ma][na][h * 2 + 1]);
        }
}

// ---------------- reduce conv2 (2-way) -> bias+relu -> bf16 NHWC ----------------
__global__ void reduce2_kernel(const float* __restrict__ part, const float* __restrict__ bias,
                               __nv_bfloat16* __restrict__ ob16) {
    size_t gid = (size_t)blockIdx.x * 256 + threadIdx.x;
    if (gid >= (size_t)43264 * 128) return;
    int p = (int)(gid >> 7);
    int oc = ((int)gid & 127) * 2;
    const float* p0 = part + (size_t)p * 256 + oc;
    const size_t half = (size_t)43264 * 256;
    float v0 = fmaxf(p0[0] + p0[half]     + bias[oc],     0.f);
    float v1 = fmaxf(p0[1] + p0[half + 1] + bias[oc + 1], 0.f);
    uint32_t w = ((uint32_t)__bfloat16_as_ushort(__float2bfloat16(v1)) << 16)
               | __bfloat16_as_ushort(__float2bfloat16(v0));
    *(uint32_t*)(ob16 + (size_t)p * 256 + oc) = w;
}

// ---------------- reduce pc partials (12-way) -> bias -> fp32 NCHW ----------------
__global__ void reducep_kernel(const float* __restrict__ part, const float* __restrict__ bias,
                               float* __restrict__ out) {
    int gid = blockIdx.x * 256 + threadIdx.x;
    if (gid >= 7744 * 64) return;
    int p = gid >> 6, oc = (gid & 63) * 4;
    const size_t seg = (size_t)7744 * 256;
    const float* p0 = part + (size_t)p * 256 + oc;
    float4 v = *(const float4*)p0;
    #pragma unroll
    for (int k = 1; k < 12; k++) {
        float4 t = *(const float4*)(p0 + k * seg);
        v.x += t.x; v.y += t.y; v.z += t.z; v.w += t.w;
    }
    const float4 bv = *(const float4*)(bias + oc);
    v.x += bv.x; v.y += bv.y; v.z += bv.z; v.w += bv.w;
    int b = p / 484;
    int rem = p - b * 484;
    int rr = rem / 22, cx = rem - rr * 22;
    size_t base = (((size_t)b * 256 + oc) * 22 + rr) * 22 + cx;
    out[base] = v.x; out[base + 484] = v.y;
    out[base + 2 * 484] = v.z; out[base + 3 * 484] = v.w;
}

// ---------------- squash ----------------
__global__ void squash_u_kernel() {
    int cap = blockIdx.x * 256 + threadIdx.x;
    if (cap >= BATCH * NI) return;
    const float4* pp = (const float4*)(g_p + (size_t)cap * 8);
    float4 a = pp[0], c = pp[1];
    float s2 = a.x*a.x + a.y*a.y + a.z*a.z + a.w*a.w + c.x*c.x + c.y*c.y + c.z*c.z + c.w*c.w;
    float f = s2 / (1.f + s2) * rsqrtf(s2 + EPSQ);
    a.x *= f; a.y *= f; a.z *= f; a.w *= f;
    c.x *= f; c.y *= f; c.z *= f; c.w *= f;
    float4* uo = (float4*)(g_u + (size_t)cap * 8);
    uo[0] = a; uo[1] = c;
}

// ---------------- u_hat (bf16 out) + fused round-1 s accumulation ----------------
// Round 1: c = softmax(0) = 1/10 exactly => s1[b,j,d] = 0.1 * sum_i u_hat[b,i,j,d]
__global__ __launch_bounds__(256)
void uhat_kernel(const float* __restrict__ W) {
    __shared__ float ssh[2560];   // [b(16)][jd(160)]
    int tid = threadIdx.x;
    for (int t = tid; t < 2560; t += 256) ssh[t] = 0.f;
    __syncthreads();

    int gid = blockIdx.x * 256 + tid;
    int d = gid & 15;
    int j = (gid >> 4) % 10;
    int i = gid / 160;
    if (i < NI) {
        const float4* Wp = (const float4*)(W + (((size_t)j * NI + i) * 16 + d) * 8);
        float4 w0 = Wp[0], w1 = Wp[1];
        for (int b = 0; b < BATCH; b++) {
            const float4* up = (const float4*)(g_u + ((size_t)b * NI + i) * 8);
            float4 u0 = up[0], u1 = up[1];
            float acc = w0.x*u0.x + w0.y*u0.y + w0.z*u0.z + w0.w*u0.w
                      + w1.x*u1.x + w1.y*u1.y + w1.z*u1.z + w1.w*u1.w;
            g_uhatb[(((size_t)b * NI + i) * 10 + j) * 16 + d] = __float2bfloat16(acc);
            atomicAdd(&ssh[b * 160 + j * 16 + d], acc);
        }
    }
    __syncthreads();
    for (int t = tid; t < 2560; t += 256)
        if (ssh[t] != 0.f) atomicAdd(&g_s[t], 0.1f * ssh[t]);
}

// ---------------- routing (rounds 2,3): s = sum_i softmax_j(u_hat*Vcum)*u_hat ----------------
__global__ __launch_bounds__(256)
void routing_s_kernel() {
    __shared__ float Vsh[160];
    __shared__ float ssh[160];
    int tid = threadIdx.x;
    int b = blockIdx.y;
    if (tid < 160) { Vsh[tid] = g_V[b * 160 + tid]; ssh[tid] = 0.f; }
    __syncthreads();
    int d = tid & 15, il = tid >> 4;
    float accj[10];
    #pragma unroll
    for (int j = 0; j < 10; j++) accj[j] = 0.f;
    const int per = NI / 32;
    int i0 = blockIdx.x * per;
    for (int i = i0 + il; i < i0 + per; i += 16) {
        const __nv_bfloat16* uh = g_uhatb + (((size_t)b * NI + i) * 10) * 16 + d;
        float uv[10], e[10];
        float m = -1e30f;
        #pragma unroll
        for (int j = 0; j < 10; j++) {
            uv[j] = __bfloat162float(uh[j * 16]);
            float l = uv[j] * Vsh[j * 16 + d];
            e[j] = l;
            m = fmaxf(m, l);
        }
        float se = 0.f;
        #pragma unroll
        for (int j = 0; j < 10; j++) { e[j] = __expf(e[j] - m); se += e[j]; }
        float inv = 1.f / se;
        #pragma unroll
        for (int j = 0; j < 10; j++) accj[j] += e[j] * inv * uv[j];
    }
    #pragma unroll
    for (int j = 0; j < 10; j++) atomicAdd(&ssh[j * 16 + d], accj[j]);
    __syncthreads();
    if (tid < 160) atomicAdd(&g_s[b * 160 + tid], ssh[tid]);
}

__global__ void v_update_kernel(int last, float* __restrict__ dout) {
    __shared__ float s2sh[10];
    __shared__ float nrm[10];
    __shared__ int amax;
    int b = blockIdx.x, tid = threadIdx.x;
    int j = tid >> 4, d = tid & 15;
    if (tid < 10) s2sh[tid] = 0.f;
    __syncthreads();
    float sv = g_s[b * 160 + tid];
    atomicAdd(&s2sh[j], sv * sv);
    __syncthreads();
    float s2 = s2sh[j];
    float v = s2 / (1.f + s2) * sv * rsqrtf(s2 + EPSQ);
    if (!last) {
        g_V[b * 160 + tid] += v;
    } else {
        if (d == 0) nrm[j] = s2 / (1.f + s2) * sqrtf(s2) * rsqrtf(s2 + EPSQ);
        __syncthreads();
        if (tid == 0) {
            int bm = 0; float mx = nrm[0];
            for (int jj = 1; jj < 10; jj++)
                if (nrm[jj] > mx) { mx = nrm[jj]; bm = jj; }
            amax = bm;
        }
        if (d == 0) dout[b * 10 + j] = nrm[j];
        __syncthreads();
        g_masked[b * 160 + tid] = (j == amax) ? v : 0.f;
    }
}

__global__ void fc_kernel(const float* __restrict__ in, const float* __restrict__ W,
                          const float* __restrict__ bias, float* __restrict__ out,
                          int IN, int OUT, int act) {
    int gid = blockIdx.x * blockDim.x + threadIdx.x;
    if (gid >= BATCH * OUT) return;
    int o = gid % OUT, b = gid / OUT;
    const float* ip = in + (size_t)b * IN;
    float acc = bias[o];
    for (int k = 0; k < IN; k++) acc += ip[k] * W[(size_t)k * OUT + o];
    if (act == 1) acc = fmaxf(acc, 0.f);
    else          acc = 1.f / (1.f + __expf(-acc));
    out[gid] = acc;
}

// ---------------- launch ----------------
extern "C" void kernel_launch(void* const* d_in, const int* in_sizes, int n_in,
                              void* d_out, int out_size) {
    const float* x   = (const float*)d_in[0];
    const float* c1w = (const float*)d_in[1];
    const float* c1b = (const float*)d_in[2];
    const float* c2w = (const float*)d_in[3];
    const float* c2b = (const float*)d_in[4];
    const float* pcw = (const float*)d_in[5];
    const float* pcb = (const float*)d_in[6];
    const float* Wc  = (const float*)d_in[7];
    const float* w1  = (const float*)d_in[8];
    const float* b1  = (const float*)d_in[9];
    const float* w2  = (const float*)d_in[10];
    const float* b2  = (const float*)d_in[11];
    const float* w3  = (const float*)d_in[12];
    const float* b3  = (const float*)d_in[13];
    float* dout = (float*)d_out;

    __nv_bfloat16 *p_c1b, *p_c2b, *p_w1b, *p_w2b, *p_wpb;
    float *p_part, *p_p, *p_s, *p_V, *p_masked, *p_d1, *p_d2;
    cudaGetSymbolAddress((void**)&p_c1b, g_c1b);
    cudaGetSymbolAddress((void**)&p_c2b, g_c2b);
    cudaGetSymbolAddress((void**)&p_part, g_part);
    cudaGetSymbolAddress((void**)&p_p,  g_p);
    cudaGetSymbolAddress((void**)&p_w1b, g_w1b);
    cudaGetSymbolAddress((void**)&p_w2b, g_w2b);
    cudaGetSymbolAddress((void**)&p_wpb, g_wpb);
    cudaGetSymbolAddress((void**)&p_s,  g_s);
    cudaGetSymbolAddress((void**)&p_V,  g_V);
    cudaGetSymbolAddress((void**)&p_masked, g_masked);
    cudaGetSymbolAddress((void**)&p_d1, g_d1);
    cudaGetSymbolAddress((void**)&p_d2, g_d2);

    auto conv2 = conv_mma_kernel<56, 56, 52, 52, 5, 1, 100, 2, 43264>;
    auto convp = conv_mma_kernel<52, 52, 22, 22, 9, 2, 324, 12, 7744>;
    cudaFuncSetAttribute(conv2, cudaFuncAttributeMaxDynamicSharedMemorySize, SMEM_CONV_TOTAL);
    cudaFuncSetAttribute(convp, cudaFuncAttributeMaxDynamicSharedMemorySize, SMEM_CONV_TOTAL);
    cudaFuncSetAttribute(conv1_mma_kernel, cudaFuncAttributeMaxDynamicSharedMemorySize, C1_SMEM);

    transform_w1_kernel<<<(2 * 64 * 128 + 255) / 256, 256>>>(c1w, p_w1b);
    transform_w_kernel<<<(100 * 64 * 128 + 255) / 256, 256>>>(c2w, p_w2b, 5, 5, 100);
    transform_w_kernel<<<(324 * 64 * 128 + 255) / 256, 256>>>(pcw, p_wpb, 9, 9, 324);

    // conv1 via MMA (K=81 padded to 128), fused bias+relu+bf16 NHWC
    conv1_mma_kernel<<<392, 512, C1_SMEM>>>(x, p_w1b, c1b, p_c1b);

    conv2<<<dim3(338, 2), 512, SMEM_CONV_TOTAL>>>(p_c1b, p_w2b, p_part);
    reduce2_kernel<<<(int)(((size_t)43264 * 128 + 255) / 256), 256>>>(p_part, c2b, p_c2b);

    convp<<<dim3(61, 12), 512, SMEM_CONV_TOTAL>>>(p_c2b, p_wpb, p_part);
    reducep_kernel<<<(7744 * 64 + 255) / 256, 256>>>(p_part, pcb, p_p);

    squash_u_kernel<<<(BATCH * NI + 255) / 256, 256>>>();

    // routing round 1 fused into uhat (c = 1/10 uniform)
    cudaMemsetAsync(p_V, 0, BATCH * 160 * sizeof(float));
    cudaMemsetAsync(p_s, 0, BATCH * 160 * sizeof(float));
    uhat_kernel<<<((size_t)NI * 160 + 255) / 256, 256>>>(Wc);
    v_update_kernel<<<16, 160>>>(0, dout);

    for (int r = 1; r < 3; r++) {
        cudaMemsetAsync(p_s, 0, BATCH * 160 * sizeof(float));
        routing_s_kernel<<<dim3(32, 16), 256>>>();
        v_update_kernel<<<16, 160>>>(r == 2 ? 1 : 0, dout);
    }

    fc_kernel<<<(BATCH * 512 + 255) / 256, 256>>>(p_masked, w1, b1, p_d1, 160, 512, 1);
    fc_kernel<<<(BATCH * 1024 + 255) / 256, 256>>>(p_d1, w2, b2, p_d2, 512, 1024, 1);
    fc_kernel<<<(BATCH * 4096 + 255) / 256, 256>>>(p_d2, w3, b3, dout + 160, 1024, 4096, 2);
}

// round 14
// speedup vs baseline: 4.9204x; 1.0120x over previous
#include <cuda_runtime.h>
#include <cuda_bf16.h>
#include <cstdint>

#define EPSQ 1e-8f
static const int BATCH = 16;
static const int NI = 15488;

// ---------------- scratch ----------------
__device__ __nv_bfloat16 g_c1b[(size_t)50176 * 256];
__device__ __nv_bfloat16 g_c2b[(size_t)43264 * 256];
__device__ float g_part[(size_t)12 * 7744 * 256];
__device__ float g_p [(size_t)16 * 256 * 22 * 22];
__device__ float g_u [(size_t)16 * 15488 * 8];
__device__ __nv_bfloat16 g_uhatb[(size_t)16 * 15488 * 10 * 16];
__device__ __nv_bfloat16 g_w1b[(size_t)2 * 16384];     // conv1: [chunk][64k x 256n swz 512B rows]
__device__ __nv_bfloat16 g_w2b[(size_t)200 * 8192];    // conv2: [chunk*2+ntile][64k x 128n swz 256B rows]
__device__ __nv_bfloat16 g_wpb[(size_t)648 * 8192];
__device__ float g_s[16 * 160];
__device__ float g_V[16 * 160];
__device__ float g_masked[16 * 160];
__device__ float g_d1[16 * 512];
__device__ float g_d2[16 * 1024];

// ---------------- helpers ----------------
__device__ __forceinline__ uint32_t smem_to_u32(const void* p) {
    uint32_t a;
    asm("{ .reg .u64 t; cvta.to.shared.u64 t, %1; cvt.u32.u64 %0, t; }" : "=r"(a) : "l"(p));
    return a;
}
__device__ __forceinline__ void ldsm_x4(uint32_t& r0, uint32_t& r1, uint32_t& r2, uint32_t& r3, uint32_t addr) {
    asm volatile("ldmatrix.sync.aligned.m8n8.x4.shared.b16 {%0,%1,%2,%3}, [%4];"
                 : "=r"(r0), "=r"(r1), "=r"(r2), "=r"(r3) : "r"(addr));
}
__device__ __forceinline__ void ldsm_x4_t(uint32_t& r0, uint32_t& r1, uint32_t& r2, uint32_t& r3, uint32_t addr) {
    asm volatile("ldmatrix.sync.aligned.m8n8.x4.trans.shared.b16 {%0,%1,%2,%3}, [%4];"
                 : "=r"(r0), "=r"(r1), "=r"(r2), "=r"(r3) : "r"(addr));
}
__device__ __forceinline__ void mma16816(float* c, const uint32_t* a, const uint32_t* b) {
    asm volatile("mma.sync.aligned.m16n8k16.row.col.f32.bf16.bf16.f32 "
                 "{%0,%1,%2,%3}, {%4,%5,%6,%7}, {%8,%9}, {%0,%1,%2,%3};"
                 : "+f"(c[0]), "+f"(c[1]), "+f"(c[2]), "+f"(c[3])
                 : "r"(a[0]), "r"(a[1]), "r"(a[2]), "r"(a[3]), "r"(b[0]), "r"(b[1]));
}
#define CP_ASYNC16(dst, src, sz) \
    asm volatile("cp.async.cg.shared.global [%0], [%1], 16, %2;" :: "r"(dst), "l"(src), "r"(sz))
#define CP_COMMIT() asm volatile("cp.async.commit_group;" ::: "memory")
#define CP_WAIT(n)  asm volatile("cp.async.wait_group %0;" :: "n"(n) : "memory")

// ---------------- weight transforms ----------------
// conv2/pc: [chunk*2+ntile][64 k x 128 n bf16, 256B rows, XOR (k&7)<<4]
__global__ void transform_w_kernel(const float* __restrict__ w,
                                   __nv_bfloat16* __restrict__ wb,
                                   int KH, int KW, int NCHUNK) {
    int idx = blockIdx.x * 256 + threadIdx.x;
    int total = NCHUNK * 2 * 64 * 64;
    if (idx >= total) return;
    int np = idx & 63;
    int k  = (idx >> 6) & 63;
    int ntile = (idx >> 12) & 1;
    int chunk = idx >> 13;
    int kyx = chunk >> 2;
    int ic = (chunk & 3) * 64 + k;
    int ky = kyx / KW, kx = kyx % KW;
    int oc = ntile * 128 + np * 2;
    size_t KHW = (size_t)KH * KW;
    size_t wi = (((size_t)oc * 256 + ic) * KH + ky) * KW + kx;
    ushort h0 = __bfloat16_as_ushort(__float2bfloat16(w[wi]));
    ushort h1 = __bfloat16_as_ushort(__float2bfloat16(w[wi + 256 * KHW]));
    int off = k * 256 + np * 4;
    int sw = off ^ ((k & 7) << 4);
    *(uint32_t*)((char*)wb + (size_t)(chunk * 2 + ntile) * 16384 + sw) = ((uint32_t)h1 << 16) | h0;
}

// conv1 weights (256,1,9,9): [chunk(2)][64k x 256n, 512B rows], k>=81 -> 0
__global__ void transform_w1_kernel(const float* __restrict__ w,
                                    __nv_bfloat16* __restrict__ wb) {
    int idx = blockIdx.x * 256 + threadIdx.x;
    if (idx >= 2 * 64 * 128) return;
    int np = idx & 127;
    int k  = (idx >> 7) & 63;
    int chunk = idx >> 13;
    int kk = chunk * 64 + k;
    int oc = np * 2;
    float f0 = (kk < 81) ? w[(size_t)oc * 81 + kk] : 0.f;
    float f1 = (kk < 81) ? w[(size_t)(oc + 1) * 81 + kk] : 0.f;
    ushort h0 = __bfloat16_as_ushort(__float2bfloat16(f0));
    ushort h1 = __bfloat16_as_ushort(__float2bfloat16(f1));
    int off = k * 512 + np * 4;
    int sw = off ^ ((k & 7) << 4);
    *(uint32_t*)((char*)wb + (size_t)chunk * 32768 + sw) = ((uint32_t)h1 << 16) | h0;
}

// ---------------- conv1 via HMMA: M=50176, N=256, K=81 pad 128 (unchanged from R13) ----------------
#define C1_STG 49152
#define C1_SMEM (2 * C1_STG)

__global__ __launch_bounds__(512, 1)
void conv1_mma_kernel(const float* __restrict__ x,
                      const __nv_bfloat16* __restrict__ wb,
                      const float* __restrict__ bias,
                      __nv_bfloat16* __restrict__ ob16) {
    extern __shared__ char smem[];
    const uint32_t sb = smem_to_u32(smem);
    const int tid = threadIdx.x;
    const int wid = tid >> 5, lid = tid & 31;
    const int tile = blockIdx.x;

    const int r = tid >> 2, sp = tid & 3;
    const int p_mine = tile * 128 + r;
    const bool pvalid = p_mine < 50176;
    int pb = 0, pr = 0, pcx = 0;
    if (pvalid) {
        pb = p_mine / 3136;
        int rem = p_mine - pb * 3136;
        pr = rem / 56;
        pcx = rem - pr * 56;
    }

    const int wm = wid >> 2, wn = wid & 3;
    const int lane15 = lid & 15, lane16 = lid >> 4;
    const int gid = lid >> 2, tig = lid & 3;

    float acc[2][8][4];
    #pragma unroll
    for (int ma = 0; ma < 2; ma++)
        #pragma unroll
        for (int na = 0; na < 8; na++)
            #pragma unroll
            for (int q = 0; q < 4; q++) acc[ma][na][q] = 0.f;

    #pragma unroll
    for (int c = 0; c < 2; c++) {
        uint32_t s0 = sb + c * C1_STG;
        const char* bsrc = (const char*)(wb + (size_t)c * 16384);
        #pragma unroll
        for (int i = 0; i < 4; i++) {
            uint32_t u = (tid + i * 512) * 16;
            CP_ASYNC16(s0 + 16384 + u, bsrc + u, 16);
        }
        const float* xb = x + (size_t)pb * 4096;
        #pragma unroll
        for (int t = 0; t < 8; t++) {
            int k0 = c * 64 + sp * 16 + 2 * t;
            float v0 = 0.f, v1 = 0.f;
            if (pvalid && k0 < 81) {
                int ky = k0 / 9, kx = k0 - 9 * ky;
                v0 = xb[(pr + ky) * 64 + pcx + kx];
            }
            if (pvalid && k0 + 1 < 81) {
                int ky = (k0 + 1) / 9, kx = (k0 + 1) - 9 * ky;
                v1 = xb[(pr + ky) * 64 + pcx + kx];
            }
            uint32_t pk = ((uint32_t)__bfloat16_as_ushort(__float2bfloat16(v1)) << 16)
                        | __bfloat16_as_ushort(__float2bfloat16(v0));
            uint32_t off = r * 128 + (sp * 16 + 2 * t) * 2;
            uint32_t sw = off ^ ((r & 7) << 4);
            *(uint32_t*)(smem + c * C1_STG + sw) = pk;
        }
    }
    CP_COMMIT();
    CP_WAIT(0);
    __syncthreads();

    #pragma unroll
    for (int c = 0; c < 2; c++) {
        const uint32_t s0 = sb + c * C1_STG;
        #pragma unroll
        for (int ks = 0; ks < 4; ks++) {
            uint32_t B[8][2];
            const int brow = ks * 16 + lane15;
            #pragma unroll
            for (int q = 0; q < 4; q++) {
                uint32_t off = brow * 512 + wn * 128 + q * 32 + lane16 * 16;
                uint32_t sw = off ^ ((brow & 7) << 4);
                ldsm_x4_t(B[2*q][0], B[2*q][1], B[2*q+1][0], B[2*q+1][1], s0 + 16384 + sw);
            }
            #pragma unroll
            for (int ma = 0; ma < 2; ma++) {
                const int arow = wm * 32 + ma * 16 + lane15;
                uint32_t offA = arow * 128 + ks * 32 + lane16 * 16;
                uint32_t swA = offA ^ ((arow & 7) << 4);
                uint32_t a[4];
                ldsm_x4(a[0], a[1], a[2], a[3], s0 + swA);
                #pragma unroll
                for (int na = 0; na < 8; na++) mma16816(acc[ma][na], a, B[na]);
            }
        }
    }

    #pragma unroll
    for (int ma = 0; ma < 2; ma++)
        #pragma unroll
        for (int h = 0; h < 2; h++) {
            int p = tile * 128 + wm * 32 + ma * 16 + h * 8 + gid;
            if (p >= 50176) continue;
            __nv_bfloat16* op = ob16 + (size_t)p * 256;
            #pragma unroll
            for (int na = 0; na < 8; na++) {
                int oc = wn * 64 + na * 8 + tig * 2;
                float v0 = fmaxf(acc[ma][na][h * 2 + 0] + bias[oc],     0.f);
                float v1 = fmaxf(acc[ma][na][h * 2 + 1] + bias[oc + 1], 0.f);
                uint32_t w = ((uint32_t)__bfloat16_as_ushort(__float2bfloat16(v1)) << 16)
                           | __bfloat16_as_ushort(__float2bfloat16(v0));
                *(uint32_t*)(op + oc) = w;
            }
        }
}

// ---------------- conv2/pc: 256 thr, 128x128 tile, 2 CTAs/SM, 3-stage ----------------
#define STG 32768
#define SMEM_CONV_TOTAL (3 * STG)

template<int IH, int IW, int OH, int OW, int KW, int STRIDE, int NCHUNK, int KSPLIT, int NPOS>
__global__ __launch_bounds__(256, 2)
void conv_mma_kernel(const __nv_bfloat16* __restrict__ inb,
                     const __nv_bfloat16* __restrict__ wb,
                     float* __restrict__ part) {
    extern __shared__ char smem[];
    const uint32_t sb = smem_to_u32(smem);
    const int tid = threadIdx.x;
    const int wid = tid >> 5, lid = tid & 31;
    const int tile = blockIdx.x, ntile = blockIdx.y;

    const int r = tid >> 1, sp = tid & 1;    // A fill: 2 thr/row, 4 x 16B segs each
    const int p_mine = tile * 128 + r;
    const bool pvalid = p_mine < NPOS;
    int pb = 0, pr = 0, pcx = 0;
    if (pvalid) {
        pb = p_mine / (OH * OW);
        int rem = p_mine - pb * (OH * OW);
        pr = rem / OW;
        pcx = rem - pr * OW;
    }
    const int asz = pvalid ? 16 : 0;

    const int wm = wid >> 1, wn = wid & 1;
    const int lane15 = lid & 15, lane16 = lid >> 4;
    const int gid = lid >> 2, tig = lid & 3;

    float acc[2][8][4];
    #pragma unroll
    for (int ma = 0; ma < 2; ma++)
        #pragma unroll
        for (int na = 0; na < 8; na++)
            #pragma unroll
            for (int q = 0; q < 4; q++) acc[ma][na][q] = 0.f;

    const int NC = NCHUNK / KSPLIT;
    const int coff = blockIdx.z * NC;

    auto fill = [&](int stage, int chunk) {
        uint32_t s0 = sb + stage * STG;
        const char* bsrc = (const char*)(wb + (size_t)(chunk * 2 + ntile) * 8192);
        #pragma unroll
        for (int i = 0; i < 4; i++) {
            uint32_t u = (tid + i * 256) * 16;
            CP_ASYNC16(s0 + 16384 + u, bsrc + u, 16);
        }
        const int kyx = chunk >> 2;
        const int ic0 = (chunk & 3) * 64;
        const int ky = kyx / KW, kx = kyx % KW;
        size_t srcbase = 0;
        if (pvalid) {
            int iy = pr * STRIDE + ky, ix = pcx * STRIDE + kx;
            srcbase = (((size_t)pb * IH + iy) * IW + ix) * 256 + ic0;
        }
        #pragma unroll
        for (int q = 0; q < 4; q++) {
            int seg = sp * 4 + q;
            uint32_t off = r * 128 + seg * 16;
            uint32_t sw = off ^ ((r & 7) << 4);
            CP_ASYNC16(s0 + sw, (const char*)(inb + srcbase + seg * 8), asz);
        }
    };

    fill(0, coff);              CP_COMMIT();
    if (NC > 1) { fill(1, coff + 1); CP_COMMIT(); }

    int st = 0;
    for (int i = 0; i < NC; ++i) {
        if (i + 1 < NC) { CP_WAIT(1); } else { CP_WAIT(0); }
        __syncthreads();

        const uint32_t s0 = sb + st * STG;
        #pragma unroll
        for (int ks = 0; ks < 4; ks++) {
            uint32_t B[8][2];
            const int brow = ks * 16 + lane15;
            #pragma unroll
            for (int q = 0; q < 4; q++) {
                uint32_t off = brow * 256 + wn * 128 + q * 32 + lane16 * 16;
                uint32_t sw = off ^ ((brow & 7) << 4);
                ldsm_x4_t(B[2*q][0], B[2*q][1], B[2*q+1][0], B[2*q+1][1], s0 + 16384 + sw);
            }
            #pragma unroll
            for (int ma = 0; ma < 2; ma++) {
                const int arow = wm * 32 + ma * 16 + lane15;
                uint32_t offA = arow * 128 + ks * 32 + lane16 * 16;
                uint32_t swA = offA ^ ((arow & 7) << 4);
                uint32_t a[4];
                ldsm_x4(a[0], a[1], a[2], a[3], s0 + swA);
                #pragma unroll
                for (int na = 0; na < 8; na++) mma16816(acc[ma][na], a, B[na]);
            }
            // overlap next-chunk fill issue with remaining MMAs of this chunk
            if (ks == 0 && i + 2 < NC) { fill((st + 2) % 3, coff + i + 2); CP_COMMIT(); }
        }
        st = (st + 1) % 3;
    }

    float* op0 = part + (size_t)blockIdx.z * NPOS * 256;
    #pragma unroll
    for (int ma = 0; ma < 2; ma++)
        #pragma unroll
        for (int h = 0; h < 2; h++) {
            int p = tile * 128 + wm * 32 + ma * 16 + h * 8 + gid;
            if (p >= NPOS) continue;
            float* op = op0 + (size_t)p * 256 + ntile * 128 + wn * 64 + tig * 2;
            #pragma unroll
            for (int na = 0; na < 8; na++)
                *(float2*)(op + na * 8) = make_float2(acc[ma][na][h * 2], acc[ma][na][h * 2 + 1]);
        }
}

// ---------------- reduce conv2 (2-way) -> bias+relu -> bf16 NHWC ----------------
__global__ void reduce2_kernel(const float* __restrict__ part, const float* __restrict__ bias,
                               __nv_bfloat16* __restrict__ ob16) {
    size_t gid = (size_t)blockIdx.x * 256 + threadIdx.x;
    if (gid >= (size_t)43264 * 128) return;
    int p = (int)(gid >> 7);
    int oc = ((int)gid & 127) * 2;
    const float* p0 = part + (size_t)p * 256 + oc;
    const size_t half = (size_t)43264 * 256;
    float v0 = fmaxf(p0[0] + p0[half]     + bias[oc],     0.f);
    float v1 = fmaxf(p0[1] + p0[half + 1] + bias[oc + 1], 0.f);
    uint32_t w = ((uint32_t)__bfloat16_as_ushort(__float2bfloat16(v1)) << 16)
               | __bfloat16_as_ushort(__float2bfloat16(v0));
    *(uint32_t*)(ob16 + (size_t)p * 256 + oc) = w;
}

// ---------------- reduce pc partials (12-way) -> bias -> fp32 NCHW ----------------
__global__ void reducep_kernel(const float* __restrict__ part, const float* __restrict__ bias,
                               float* __restrict__ out) {
    int gid = blockIdx.x * 256 + threadIdx.x;
    if (gid >= 7744 * 64) return;
    int p = gid >> 6, oc = (gid & 63) * 4;
    const size_t seg = (size_t)7744 * 256;
    const float* p0 = part + (size_t)p * 256 + oc;
    float4 v = *(const float4*)p0;
    #pragma unroll
    for (int k = 1; k < 12; k++) {
        float4 t = *(const float4*)(p0 + k * seg);
        v.x += t.x; v.y += t.y; v.z += t.z; v.w += t.w;
    }
    const float4 bv = *(const float4*)(bias + oc);
    v.x += bv.x; v.y += bv.y; v.z += bv.z; v.w += bv.w;
    int b = p / 484;
    int rem = p - b * 484;
    int rr = rem / 22, cx = rem - rr * 22;
    size_t base = (((size_t)b * 256 + oc) * 22 + rr) * 22 + cx;
    out[base] = v.x; out[base + 484] = v.y;
    out[base + 2 * 484] = v.z; out[base + 3 * 484] = v.w;
}

// ---------------- squash ----------------
__global__ void squash_u_kernel() {
    int cap = blockIdx.x * 256 + threadIdx.x;
    if (cap >= BATCH * NI) return;
    const float4* pp = (const float4*)(g_p + (size_t)cap * 8);
    float4 a = pp[0], c = pp[1];
    float s2 = a.x*a.x + a.y*a.y + a.z*a.z + a.w*a.w + c.x*c.x + c.y*c.y + c.z*c.z + c.w*c.w;
    float f = s2 / (1.f + s2) * rsqrtf(s2 + EPSQ);
    a.x *= f; a.y *= f; a.z *= f; a.w *= f;
    c.x *= f; c.y *= f; c.z *= f; c.w *= f;
    float4* uo = (float4*)(g_u + (size_t)cap * 8);
    uo[0] = a; uo[1] = c;
}

// ---------------- u_hat (bf16) + fused round-1 s ----------------
__global__ __launch_bounds__(256)
void uhat_kernel(const float* __restrict__ W) {
    __shared__ float ssh[2560];
    int tid = threadIdx.x;
    for (int t = tid; t < 2560; t += 256) ssh[t] = 0.f;
    __syncthreads();

    int gid = blockIdx.x * 256 + tid;
    int d = gid & 15;
    int j = (gid >> 4) % 10;
    int i = gid / 160;
    if (i < NI) {
        const float4* Wp = (const float4*)(W + (((size_t)j * NI + i) * 16 + d) * 8);
        float4 w0 = Wp[0], w1 = Wp[1];
        for (int b = 0; b < BATCH; b++) {
            const float4* up = (const float4*)(g_u + ((size_t)b * NI + i) * 8);
            float4 u0 = up[0], u1 = up[1];
            float acc = w0.x*u0.x + w0.y*u0.y + w0.z*u0.z + w0.w*u0.w
                      + w1.x*u1.x + w1.y*u1.y + w1.z*u1.z + w1.w*u1.w;
            g_uhatb[(((size_t)b * NI + i) * 10 + j) * 16 + d] = __float2bfloat16(acc);
            atomicAdd(&ssh[b * 160 + j * 16 + d], acc);
        }
    }
    __syncthreads();
    for (int t = tid; t < 2560; t += 256)
        if (ssh[t] != 0.f) atomicAdd(&g_s[t], 0.1f * ssh[t]);
}

// ---------------- routing (rounds 2,3) ----------------
__global__ __launch_bounds__(256)
void routing_s_kernel() {
    __shared__ float Vsh[160];
    __shared__ float ssh[160];
    int tid = threadIdx.x;
    int b = blockIdx.y;
    if (tid < 160) { Vsh[tid] = g_V[b * 160 + tid]; ssh[tid] = 0.f; }
    __syncthreads();
    int d = tid & 15, il = tid >> 4;
    float accj[10];
    #pragma unroll
    for (int j = 0; j < 10; j++) accj[j] = 0.f;
    const int per = NI / 32;
    int i0 = blockIdx.x * per;
    for (int i = i0 + il; i < i0 + per; i += 16) {
        const __nv_bfloat16* uh = g_uhatb + (((size_t)b * NI + i) * 10) * 16 + d;
        float uv[10], e[10];
        float m = -1e30f;
        #pragma unroll
        for (int j = 0; j < 10; j++) {
            uv[j] = __bfloat162float(uh[j * 16]);
            float l = uv[j] * Vsh[j * 16 + d];
            e[j] = l;
            m = fmaxf(m, l);
        }
        float se = 0.f;
        #pragma unroll
        for (int j = 0; j < 10; j++) { e[j] = __expf(e[j] - m); se += e[j]; }
        float inv = 1.f / se;
        #pragma unroll
        for (int j = 0; j < 10; j++) accj[j] += e[j] * inv * uv[j];
    }
    #pragma unroll
    for (int j = 0; j < 10; j++) atomicAdd(&ssh[j * 16 + d], accj[j]);
    __syncthreads();
    if (tid < 160) atomicAdd(&g_s[b * 160 + tid], ssh[tid]);
}

__global__ void v_update_kernel(int last, float* __restrict__ dout) {
    __shared__ float s2sh[10];
    __shared__ float nrm[10];
    __shared__ int amax;
    int b = blockIdx.x, tid = threadIdx.x;
    int j = tid >> 4, d = tid & 15;
    if (tid < 10) s2sh[tid] = 0.f;
    __syncthreads();
    float sv = g_s[b * 160 + tid];
    atomicAdd(&s2sh[j], sv * sv);
    __syncthreads();
    float s2 = s2sh[j];
    float v = s2 / (1.f + s2) * sv * rsqrtf(s2 + EPSQ);
    if (!last) {
        g_V[b * 160 + tid] += v;
    } else {
        if (d == 0) nrm[j] = s2 / (1.f + s2) * sqrtf(s2) * rsqrtf(s2 + EPSQ);
        __syncthreads();
        if (tid == 0) {
            int bm = 0; float mx = nrm[0];
            for (int jj = 1; jj < 10; jj++)
                if (nrm[jj] > mx) { mx = nrm[jj]; bm = jj; }
            amax = bm;
        }
        if (d == 0) dout[b * 10 + j] = nrm[j];
        __syncthreads();
        g_masked[b * 160 + tid] = (j == amax) ? v : 0.f;
    }
}

__global__ void fc_kernel(const float* __restrict__ in, const float* __restrict__ W,
                          const float* __restrict__ bias, float* __restrict__ out,
                          int IN, int OUT, int act) {
    int gid = blockIdx.x * blockDim.x + threadIdx.x;
    if (gid >= BATCH * OUT) return;
    int o = gid % OUT, b = gid / OUT;
    const float* ip = in + (size_t)b * IN;
    float acc = bias[o];
    for (int k = 0; k < IN; k++) acc += ip[k] * W[(size_t)k * OUT + o];
    if (act == 1) acc = fmaxf(acc, 0.f);
    else          acc = 1.f / (1.f + __expf(-acc));
    out[gid] = acc;
}

// ---------------- launch ----------------
extern "C" void kernel_launch(void* const* d_in, const int* in_sizes, int n_in,
                              void* d_out, int out_size) {
    const float* x   = (const float*)d_in[0];
    const float* c1w = (const float*)d_in[1];
    const float* c1b = (const float*)d_in[2];
    const float* c2w = (const float*)d_in[3];
    const float* c2b = (const float*)d_in[4];
    const float* pcw = (const float*)d_in[5];
    const float* pcb = (const float*)d_in[6];
    const float* Wc  = (const float*)d_in[7];
    const float* w1  = (const float*)d_in[8];
    const float* b1  = (const float*)d_in[9];
    const float* w2  = (const float*)d_in[10];
    const float* b2  = (const float*)d_in[11];
    const float* w3  = (const float*)d_in[12];
    const float* b3  = (const float*)d_in[13];
    float* dout = (float*)d_out;

    __nv_bfloat16 *p_c1b, *p_c2b, *p_w1b, *p_w2b, *p_wpb;
    float *p_part, *p_p, *p_s, *p_V, *p_masked, *p_d1, *p_d2;
    cudaGetSymbolAddress((void**)&p_c1b, g_c1b);
    cudaGetSymbolAddress((void**)&p_c2b, g_c2b);
    cudaGetSymbolAddress((void**)&p_part, g_part);
    cudaGetSymbolAddress((void**)&p_p,  g_p);
    cudaGetSymbolAddress((void**)&p_w1b, g_w1b);
    cudaGetSymbolAddress((void**)&p_w2b, g_w2b);
    cudaGetSymbolAddress((void**)&p_wpb, g_wpb);
    cudaGetSymbolAddress((void**)&p_s,  g_s);
    cudaGetSymbolAddress((void**)&p_V,  g_V);
    cudaGetSymbolAddress((void**)&p_masked, g_masked);
    cudaGetSymbolAddress((void**)&p_d1, g_d1);
    cudaGetSymbolAddress((void**)&p_d2, g_d2);

    auto conv2 = conv_mma_kernel<56, 56, 52, 52, 5, 1, 100, 2, 43264>;
    auto convp = conv_mma_kernel<52, 52, 22, 22, 9, 2, 324, 12, 7744>;
    cudaFuncSetAttribute(conv2, cudaFuncAttributeMaxDynamicSharedMemorySize, SMEM_CONV_TOTAL);
    cudaFuncSetAttribute(convp, cudaFuncAttributeMaxDynamicSharedMemorySize, SMEM_CONV_TOTAL);
    cudaFuncSetAttribute(conv1_mma_kernel, cudaFuncAttributeMaxDynamicSharedMemorySize, C1_SMEM);

    transform_w1_kernel<<<(2 * 64 * 128 + 255) / 256, 256>>>(c1w, p_w1b);
    transform_w_kernel<<<(100 * 8192 + 255) / 256, 256>>>(c2w, p_w2b, 5, 5, 100);
    transform_w_kernel<<<(324 * 8192 + 255) / 256, 256>>>(pcw, p_wpb, 9, 9, 324);

    conv1_mma_kernel<<<392, 512, C1_SMEM>>>(x, p_w1b, c1b, p_c1b);

    conv2<<<dim3(338, 2, 2), 256, SMEM_CONV_TOTAL>>>(p_c1b, p_w2b, p_part);
    reduce2_kernel<<<(int)(((size_t)43264 * 128 + 255) / 256), 256>>>(p_part, c2b, p_c2b);

    convp<<<dim3(61, 2, 12), 256, SMEM_CONV_TOTAL>>>(p_c2b, p_wpb, p_part);
    reducep_kernel<<<(7744 * 64 + 255) / 256, 256>>>(p_part, pcb, p_p);

    squash_u_kernel<<<(BATCH * NI + 255) / 256, 256>>>();

    cudaMemsetAsync(p_V, 0, BATCH * 160 * sizeof(float));
    cudaMemsetAsync(p_s, 0, BATCH * 160 * sizeof(float));
    uhat_kernel<<<((size_t)NI * 160 + 255) / 256, 256>>>(Wc);
    v_update_kernel<<<16, 160>>>(0, dout);

    for (int r = 1; r < 3; r++) {
        cudaMemsetAsync(p_s, 0, BATCH * 160 * sizeof(float));
        routing_s_kernel<<<dim3(32, 16), 256>>>();
        v_update_kernel<<<16, 160>>>(r == 2 ? 1 : 0, dout);
    }

    fc_kernel<<<(BATCH * 512 + 255) / 256, 256>>>(p_masked, w1, b1, p_d1, 160, 512, 1);
    fc_kernel<<<(BATCH * 1024 + 255) / 256, 256>>>(p_d1, w2, b2, p_d2, 512, 1024, 1);
    fc_kernel<<<(BATCH * 4096 + 255) / 256, 256>>>(p_d2, w3, b3, dout + 160, 1024, 4096, 2);
}